// round 3
// baseline (speedup 1.0000x reference)
#include <cuda_runtime.h>

// ----------------------------------------------------------------------------
// Swin block: LN1 -> shift+window -> QKV -> W-MSA(+rel bias,+mask) -> proj
//             -> reverse+roll -> +residual -> LN2 -> fc1+GELU -> fc2 -> +residual
// Shapes: B=16, H=W=56, C=256, NH=8, HD=32, WS=7, N=49, nW=64, Bw=1024
// ----------------------------------------------------------------------------

#define DEVFN __device__ __forceinline__

constexpr int TOKENS = 16 * 56 * 56;   // 50176
constexpr float SCALE = 0.17677669529663687f;   // 32^-0.5

// Scratch (static device arrays: allocation-free per harness rules)
__device__ float g_hw [TOKENS * 256];   // LN1'd, shifted, window-partitioned
__device__ float g_q  [TOKENS * 256];   // (wb, h, n, d), pre-scaled
__device__ float g_k  [TOKENS * 256];
__device__ float g_v  [TOKENS * 256];
__device__ float g_o  [TOKENS * 256];   // attention out, (wb, n, h*32+d)
__device__ float g_x2 [TOKENS * 256];   // post-attn residual, natural token order
__device__ float g_h2n[TOKENS * 256];   // LN2 output
__device__ float g_mlp[TOKENS * 1024];  // fc1+gelu output

// ---------------- packed f32x2 helpers (Blackwell FFMA2 path) ----------------
DEVFN unsigned long long pk2(float lo, float hi) {
    unsigned long long r;
    asm("mov.b64 %0, {%1, %2};" : "=l"(r) : "f"(lo), "f"(hi));
    return r;
}
DEVFN void upk2(unsigned long long v, float& lo, float& hi) {
    asm("mov.b64 {%0, %1}, %2;" : "=f"(lo), "=f"(hi) : "l"(v));
}
DEVFN void fma2(unsigned long long& a, unsigned long long x, unsigned long long y) {
    asm("fma.rn.f32x2 %0, %1, %2, %0;" : "+l"(a) : "l"(x), "l"(y));
}

// ---------------- LayerNorm (optionally fused with shift+window scatter) -----
__global__ void __launch_bounds__(256) ln_kernel(
    const float* __restrict__ in, float* __restrict__ out,
    const float* __restrict__ gamma, const float* __restrict__ beta,
    int shifted)
{
    int t = blockIdx.x;
    int in_row, out_row;
    if (shifted) {
        // output coords (b, i, j) in SHIFTED frame; read rolled input; write windowed
        int b = t / 3136; int rem = t - b * 3136;
        int i = rem / 56; int j = rem - i * 56;
        int si = i + 3; if (si >= 56) si -= 56;
        int sj = j + 3; if (sj >= 56) sj -= 56;
        in_row = b * 3136 + si * 56 + sj;
        int wb = b * 64 + (i / 7) * 8 + (j / 7);
        int n  = (i % 7) * 7 + (j % 7);
        out_row = wb * 49 + n;
    } else {
        in_row = out_row = t;
    }
    int c = threadIdx.x;
    float v = in[(size_t)in_row * 256 + c];
    float s = v, sq = v * v;
    #pragma unroll
    for (int o = 16; o; o >>= 1) {
        s  += __shfl_xor_sync(0xffffffffu, s,  o);
        sq += __shfl_xor_sync(0xffffffffu, sq, o);
    }
    __shared__ float rs[8], rq[8];
    int warp = c >> 5, lane = c & 31;
    if (lane == 0) { rs[warp] = s; rq[warp] = sq; }
    __syncthreads();
    s = 0.f; sq = 0.f;
    #pragma unroll
    for (int w = 0; w < 8; w++) { s += rs[w]; sq += rq[w]; }
    float mu   = s * (1.0f / 256.0f);
    float var  = sq * (1.0f / 256.0f) - mu * mu;
    float rstd = rsqrtf(var + 1e-5f);
    out[(size_t)out_row * 256 + c] = (v - mu) * rstd * gamma[c] + beta[c];
}

// ---------------- Windowed attention: one block per (window, head) -----------
__global__ void __launch_bounds__(256) attn_kernel(
    const float* __restrict__ rel_bias, const float* __restrict__ mask)
{
    int wb = blockIdx.x >> 3;
    int h  = blockIdx.x & 7;
    __shared__ float qs[49 * 32];
    __shared__ float ks[49 * 33];   // padded: stride-32 reads in QK^T would be 32-way conflicts
    __shared__ float vs[49 * 32];
    __shared__ float sc[49 * 49];

    size_t base = (size_t)blockIdx.x * (49 * 32);
    for (int idx = threadIdx.x; idx < 49 * 32; idx += 256) {
        int r = idx >> 5, d = idx & 31;
        qs[idx]        = g_q[base + idx];
        ks[r * 33 + d] = g_k[base + idx];
        vs[idx]        = g_v[base + idx];
    }
    __syncthreads();

    const float* mrow = mask + (size_t)(wb & 63) * 2401;
    for (int e = threadIdx.x; e < 2401; e += 256) {
        int qn = e / 49; int km = e - qn * 49;
        const float* qp = qs + qn * 32;
        const float* kp = ks + km * 33;
        float d = 0.f;
        #pragma unroll
        for (int dd = 0; dd < 32; dd++) d += qp[dd] * kp[dd];
        int qi = qn / 7, qj = qn - qi * 7;
        int ki = km / 7, kj = km - ki * 7;
        int ridx = (qi - ki + 6) * 13 + (qj - kj + 6);
        sc[e] = d + rel_bias[ridx * 8 + h] + mrow[e];
    }
    __syncthreads();

    int warp = threadIdx.x >> 5, lane = threadIdx.x & 31;
    for (int row = warp; row < 49; row += 8) {
        float* r = sc + row * 49;
        float m = -1e30f;
        for (int cidx = lane; cidx < 49; cidx += 32) m = fmaxf(m, r[cidx]);
        #pragma unroll
        for (int o = 16; o; o >>= 1) m = fmaxf(m, __shfl_xor_sync(0xffffffffu, m, o));
        float s = 0.f;
        for (int cidx = lane; cidx < 49; cidx += 32) {
            float e2 = __expf(r[cidx] - m); r[cidx] = e2; s += e2;
        }
        #pragma unroll
        for (int o = 16; o; o >>= 1) s += __shfl_xor_sync(0xffffffffu, s, o);
        float inv = 1.0f / s;
        for (int cidx = lane; cidx < 49; cidx += 32) r[cidx] *= inv;
    }
    __syncthreads();

    for (int idx = threadIdx.x; idx < 49 * 32; idx += 256) {
        int n = idx >> 5, dd = idx & 31;
        const float* pr = sc + n * 49;
        float acc = 0.f;
        #pragma unroll
        for (int m2 = 0; m2 < 49; m2++) acc += pr[m2] * vs[m2 * 32 + dd];
        g_o[((size_t)(wb * 49 + n)) * 256 + h * 32 + dd] = acc;
    }
}

// ---------------- SGEMM NT (A[M,K] * B[N,K]^T), 128x128x8, fma.rn.f32x2 ------
// MODE 0: QKV  (bias; scatter to q*SCALE / k / v in (wb,h,n,d) layout)
// MODE 1: proj (bias; window-reverse + un-roll; + residual from `res`)
// MODE 2: fc1  (bias; exact GELU)
// MODE 3: fc2  (bias; + residual from `res`, natural row order)
template <int MODE>
__global__ void __launch_bounds__(256, 2) sgemm_nt(
    const float* __restrict__ A, const float* __restrict__ B,
    const float* __restrict__ bias, const float* __restrict__ res,
    float* __restrict__ O0, float* __restrict__ O1, float* __restrict__ O2,
    int M, int N, int K)
{
    __shared__ float As[8][128];
    __shared__ float Bs[8][128];
    const int t  = threadIdx.x;
    const int tx = t & 15;
    const int ty = t >> 4;
    const int rowBase = blockIdx.y * 128;
    const int colBase = blockIdx.x * 128;
    const int lr = t >> 1;
    const int lk = (t & 1) * 4;
    const float* Ap = A + (size_t)(rowBase + lr) * K + lk;
    const float* Bp = B + (size_t)(colBase + lr) * K + lk;

    unsigned long long acc[8][4];
    #pragma unroll
    for (int i = 0; i < 8; i++)
        #pragma unroll
        for (int j = 0; j < 4; j++) acc[i][j] = 0ull;

    for (int k0 = 0; k0 < K; k0 += 8) {
        float4 a4 = *(const float4*)(Ap + k0);
        float4 b4 = *(const float4*)(Bp + k0);
        As[lk + 0][lr] = a4.x; As[lk + 1][lr] = a4.y;
        As[lk + 2][lr] = a4.z; As[lk + 3][lr] = a4.w;
        Bs[lk + 0][lr] = b4.x; Bs[lk + 1][lr] = b4.y;
        Bs[lk + 2][lr] = b4.z; Bs[lk + 3][lr] = b4.w;
        __syncthreads();
        #pragma unroll
        for (int kk = 0; kk < 8; kk++) {
            float4 a0 = *(const float4*)&As[kk][ty * 8];
            float4 a1 = *(const float4*)&As[kk][ty * 8 + 4];
            float4 b0 = *(const float4*)&Bs[kk][tx * 8];
            float4 b1 = *(const float4*)&Bs[kk][tx * 8 + 4];
            unsigned long long bp0 = pk2(b0.x, b0.y);
            unsigned long long bp1 = pk2(b0.z, b0.w);
            unsigned long long bp2 = pk2(b1.x, b1.y);
            unsigned long long bp3 = pk2(b1.z, b1.w);
            float av[8] = {a0.x, a0.y, a0.z, a0.w, a1.x, a1.y, a1.z, a1.w};
            #pragma unroll
            for (int i = 0; i < 8; i++) {
                unsigned long long ad = pk2(av[i], av[i]);
                fma2(acc[i][0], ad, bp0);
                fma2(acc[i][1], ad, bp1);
                fma2(acc[i][2], ad, bp2);
                fma2(acc[i][3], ad, bp3);
            }
        }
        __syncthreads();
    }

    #pragma unroll
    for (int i = 0; i < 8; i++) {
        int gm = rowBase + ty * 8 + i;
        float cv[8];
        #pragma unroll
        for (int jp = 0; jp < 4; jp++) upk2(acc[i][jp], cv[2 * jp], cv[2 * jp + 1]);

        if (MODE == 0) {
            int wb = gm / 49; int n = gm - wb * 49;
            #pragma unroll
            for (int j = 0; j < 8; j++) {
                int gc = colBase + tx * 8 + j;
                float v = cv[j] + bias[gc];
                int part = gc >> 8;
                int hh = (gc >> 5) & 7;
                int dd = gc & 31;
                size_t dst = (((size_t)wb * 8 + hh) * 49 + n) * 32 + dd;
                if (part == 0)      O0[dst] = v * SCALE;
                else if (part == 1) O1[dst] = v;
                else                O2[dst] = v;
            }
        } else if (MODE == 1) {
            int wb = gm / 49; int n = gm - wb * 49;
            int b = wb >> 6; int widx = wb & 63;
            int ii = (widx >> 3) * 7 + n / 7;
            int jj = (widx & 7) * 7 + n % 7;
            int oi = ii + 3; if (oi >= 56) oi -= 56;
            int oj = jj + 3; if (oj >= 56) oj -= 56;
            size_t orow = ((size_t)b * 3136 + oi * 56 + oj) * 256;
            #pragma unroll
            for (int j = 0; j < 8; j++) {
                int gc = colBase + tx * 8 + j;
                O0[orow + gc] = res[orow + gc] + cv[j] + bias[gc];
            }
        } else if (MODE == 2) {
            size_t orow = (size_t)gm * N;
            #pragma unroll
            for (int j = 0; j < 8; j++) {
                int gc = colBase + tx * 8 + j;
                float v = cv[j] + bias[gc];
                v = 0.5f * v * (1.0f + erff(v * 0.70710678118654752f));
                O0[orow + gc] = v;
            }
        } else {
            size_t orow = (size_t)gm * N;
            #pragma unroll
            for (int j = 0; j < 8; j++) {
                int gc = colBase + tx * 8 + j;
                O0[orow + gc] = res[orow + gc] + cv[j] + bias[gc];
            }
        }
    }
}

// ----------------------------------------------------------------------------
extern "C" void kernel_launch(void* const* d_in, const int* in_sizes, int n_in,
                              void* d_out, int out_size)
{
    const float* x      = (const float*)d_in[0];
    const float* mask   = (const float*)d_in[1];
    const float* n1g    = (const float*)d_in[2];
    const float* n1b    = (const float*)d_in[3];
    const float* qkv_w  = (const float*)d_in[4];
    const float* qkv_b  = (const float*)d_in[5];
    const float* relb   = (const float*)d_in[6];
    const float* proj_w = (const float*)d_in[7];
    const float* proj_b = (const float*)d_in[8];
    const float* n2g    = (const float*)d_in[9];
    const float* n2b    = (const float*)d_in[10];
    const float* fc1_w  = (const float*)d_in[11];
    const float* fc1_b  = (const float*)d_in[12];
    const float* fc2_w  = (const float*)d_in[13];
    const float* fc2_b  = (const float*)d_in[14];
    float* out = (float*)d_out;

    float *p_hw, *p_q, *p_k, *p_v, *p_o, *p_x2, *p_h2n, *p_mlp;
    cudaGetSymbolAddress((void**)&p_hw,  g_hw);
    cudaGetSymbolAddress((void**)&p_q,   g_q);
    cudaGetSymbolAddress((void**)&p_k,   g_k);
    cudaGetSymbolAddress((void**)&p_v,   g_v);
    cudaGetSymbolAddress((void**)&p_o,   g_o);
    cudaGetSymbolAddress((void**)&p_x2,  g_x2);
    cudaGetSymbolAddress((void**)&p_h2n, g_h2n);
    cudaGetSymbolAddress((void**)&p_mlp, g_mlp);

    // 1. LN1 + cyclic shift + window partition
    ln_kernel<<<TOKENS, 256>>>(x, p_hw, n1g, n1b, 1);
    // 2. QKV projection -> q(scaled)/k/v in (wb, h, n, d)
    sgemm_nt<0><<<dim3(6, 392), 256>>>(p_hw, qkv_w, qkv_b, nullptr,
                                       p_q, p_k, p_v, TOKENS, 768, 256);
    // 3. Windowed MSA with relative position bias + shift mask
    attn_kernel<<<8192, 256>>>(relb, mask);
    // 4. Output projection + window-reverse + un-roll + residual (x)
    sgemm_nt<1><<<dim3(2, 392), 256>>>(p_o, proj_w, proj_b, x,
                                       p_x2, nullptr, nullptr, TOKENS, 256, 256);
    // 5. LN2
    ln_kernel<<<TOKENS, 256>>>(p_x2, p_h2n, n2g, n2b, 0);
    // 6. fc1 + GELU
    sgemm_nt<2><<<dim3(8, 392), 256>>>(p_h2n, fc1_w, fc1_b, nullptr,
                                       p_mlp, nullptr, nullptr, TOKENS, 1024, 256);
    // 7. fc2 + residual (x2) -> out
    sgemm_nt<3><<<dim3(2, 392), 256>>>(p_mlp, fc2_w, fc2_b, p_x2,
                                       out, nullptr, nullptr, TOKENS, 256, 1024);
}

// round 6
// speedup vs baseline: 2.5782x; 2.5782x over previous
#include <cuda_runtime.h>
#include <cstdint>

#define DEVFN __device__ __forceinline__

constexpr int TOKENS = 16 * 56 * 56;   // 50176
constexpr float SCALE = 0.17677669529663687f;   // 32^-0.5

// Scratch (static device arrays: allocation-free per harness rules)
__device__ float g_hw  [TOKENS * 256];
__device__ float g_q   [TOKENS * 256];
__device__ float g_k   [TOKENS * 256];
__device__ float g_v   [TOKENS * 256];
__device__ float g_o   [TOKENS * 256];
__device__ float g_x2  [TOKENS * 256];
__device__ float g_h2n [TOKENS * 256];
__device__ float g_mlp [TOKENS * 1024];
__device__ float g_wqkv[768 * 256];
__device__ float g_wprj[256 * 256];
__device__ float g_wfc1[1024 * 256];
__device__ float g_wfc2[256 * 1024];

// ------------------------------ PTX helpers ---------------------------------
DEVFN uint32_t smem_u32(const void* p) {
    uint32_t a;
    asm("{ .reg .u64 t; cvta.to.shared.u64 t, %1; cvt.u32.u64 %0, t; }"
        : "=r"(a) : "l"(p));
    return a;
}
DEVFN uint32_t swz(uint32_t o) { return o ^ ((o >> 3) & 0x70u); }
DEVFN void cp16(uint32_t dst, const void* src) {
    asm volatile("cp.async.cg.shared.global [%0], [%1], 16;" :: "r"(dst), "l"(src));
}
DEVFN void cp_commit() { asm volatile("cp.async.commit_group;" ::: "memory"); }
template <int N> DEVFN void cp_wait() {
    asm volatile("cp.async.wait_group %0;" :: "n"(N) : "memory");
}
DEVFN float to_tf32(float x) {
    float r;
    asm("cvt.rna.tf32.f32 %0, %1;" : "=f"(r) : "f"(x));
    return r;
}
DEVFN void mma8(float c[4], const uint32_t a[4], const uint32_t b[2]) {
    asm volatile(
        "mma.sync.aligned.m16n8k8.row.col.f32.tf32.tf32.f32 "
        "{%0,%1,%2,%3}, {%4,%5,%6,%7}, {%8,%9}, {%0,%1,%2,%3};"
        : "+f"(c[0]), "+f"(c[1]), "+f"(c[2]), "+f"(c[3])
        : "r"(a[0]), "r"(a[1]), "r"(a[2]), "r"(a[3]), "r"(b[0]), "r"(b[1]));
}

// ---------------- weight pre-round to tf32 (RNA) -----------------------------
__global__ void __launch_bounds__(256) wcvt(const float4* __restrict__ s,
                                            float4* __restrict__ d, int n4)
{
    int i = blockIdx.x * 256 + threadIdx.x;
    if (i < n4) {
        float4 v = s[i];
        v.x = to_tf32(v.x); v.y = to_tf32(v.y);
        v.z = to_tf32(v.z); v.w = to_tf32(v.w);
        d[i] = v;
    }
}

// ---------------- LayerNorm (warp/row; outputs pre-rounded to tf32) ----------
__global__ void __launch_bounds__(256) ln_kernel(
    const float* __restrict__ in, float* __restrict__ out,
    const float* __restrict__ gamma, const float* __restrict__ beta,
    int shifted)
{
    int warp = threadIdx.x >> 5, lane = threadIdx.x & 31;
    int t = blockIdx.x * 8 + warp;
    int in_row, out_row;
    if (shifted) {
        int b = t / 3136; int rem = t - b * 3136;
        int i = rem / 56; int j = rem - i * 56;
        int si = i + 3; if (si >= 56) si -= 56;
        int sj = j + 3; if (sj >= 56) sj -= 56;
        in_row = b * 3136 + si * 56 + sj;
        int wb = b * 64 + (i / 7) * 8 + (j / 7);
        int n  = (i % 7) * 7 + (j % 7);
        out_row = wb * 49 + n;
    } else {
        in_row = out_row = t;
    }
    const float4* ip = (const float4*)(in + (size_t)in_row * 256);
    float4 a = ip[lane], b4 = ip[lane + 32];
    float s  = a.x + a.y + a.z + a.w + b4.x + b4.y + b4.z + b4.w;
    float sq = a.x*a.x + a.y*a.y + a.z*a.z + a.w*a.w
             + b4.x*b4.x + b4.y*b4.y + b4.z*b4.z + b4.w*b4.w;
    #pragma unroll
    for (int o = 16; o; o >>= 1) {
        s  += __shfl_xor_sync(0xffffffffu, s,  o);
        sq += __shfl_xor_sync(0xffffffffu, sq, o);
    }
    float mu   = s * (1.0f / 256.0f);
    float var  = sq * (1.0f / 256.0f) - mu * mu;
    float rstd = rsqrtf(var + 1e-5f);
    float4 g0 = ((const float4*)gamma)[lane], g1 = ((const float4*)gamma)[lane + 32];
    float4 e0 = ((const float4*)beta)[lane],  e1 = ((const float4*)beta)[lane + 32];
    float4 o0, o1;
    o0.x = to_tf32((a.x - mu) * rstd * g0.x + e0.x);
    o0.y = to_tf32((a.y - mu) * rstd * g0.y + e0.y);
    o0.z = to_tf32((a.z - mu) * rstd * g0.z + e0.z);
    o0.w = to_tf32((a.w - mu) * rstd * g0.w + e0.w);
    o1.x = to_tf32((b4.x - mu) * rstd * g1.x + e1.x);
    o1.y = to_tf32((b4.y - mu) * rstd * g1.y + e1.y);
    o1.z = to_tf32((b4.z - mu) * rstd * g1.z + e1.z);
    o1.w = to_tf32((b4.w - mu) * rstd * g1.w + e1.w);
    float4* op = (float4*)(out + (size_t)out_row * 256);
    op[lane] = o0; op[lane + 32] = o1;
}

// ---------------- Windowed attention: one block per (window, head) -----------
__global__ void __launch_bounds__(256) attn_kernel(
    const float* __restrict__ rel_bias, const float* __restrict__ mask)
{
    int wb = blockIdx.x >> 3;
    int h  = blockIdx.x & 7;
    __shared__ float qs[49 * 32];
    __shared__ float ks[49 * 33];
    __shared__ float vs[49 * 32];
    __shared__ float sc[49 * 49];

    size_t base = (size_t)blockIdx.x * (49 * 32);
    for (int idx = threadIdx.x; idx < 49 * 32; idx += 256) {
        int r = idx >> 5, d = idx & 31;
        qs[idx]        = g_q[base + idx];
        ks[r * 33 + d] = g_k[base + idx];
        vs[idx]        = g_v[base + idx];
    }
    __syncthreads();

    const float* mrow = mask + (size_t)(wb & 63) * 2401;
    for (int e = threadIdx.x; e < 2401; e += 256) {
        int qn = e / 49; int km = e - qn * 49;
        const float* qp = qs + qn * 32;
        const float* kp = ks + km * 33;
        float d = 0.f;
        #pragma unroll
        for (int dd = 0; dd < 32; dd++) d += qp[dd] * kp[dd];
        int qi = qn / 7, qj = qn - qi * 7;
        int ki = km / 7, kj = km - ki * 7;
        int ridx = (qi - ki + 6) * 13 + (qj - kj + 6);
        sc[e] = d + rel_bias[ridx * 8 + h] + mrow[e];
    }
    __syncthreads();

    int warp = threadIdx.x >> 5, lane = threadIdx.x & 31;
    for (int row = warp; row < 49; row += 8) {
        float* r = sc + row * 49;
        float m = -1e30f;
        for (int cidx = lane; cidx < 49; cidx += 32) m = fmaxf(m, r[cidx]);
        #pragma unroll
        for (int o = 16; o; o >>= 1) m = fmaxf(m, __shfl_xor_sync(0xffffffffu, m, o));
        float s = 0.f;
        for (int cidx = lane; cidx < 49; cidx += 32) {
            float e2 = __expf(r[cidx] - m); r[cidx] = e2; s += e2;
        }
        #pragma unroll
        for (int o = 16; o; o >>= 1) s += __shfl_xor_sync(0xffffffffu, s, o);
        float inv = 1.0f / s;
        for (int cidx = lane; cidx < 49; cidx += 32) r[cidx] *= inv;
    }
    __syncthreads();

    for (int idx = threadIdx.x; idx < 49 * 32; idx += 256) {
        int n = idx >> 5, dd = idx & 31;
        const float* pr = sc + n * 49;
        float acc = 0.f;
        #pragma unroll
        for (int m2 = 0; m2 < 49; m2++) acc += pr[m2] * vs[m2 * 32 + dd];
        g_o[((size_t)(wb * 49 + n)) * 256 + h * 32 + dd] = to_tf32(acc);
    }
}

// ---------------- tf32 mma.sync GEMM NT, 128x128 tile, K-chunk 32 ------------
// D[M,N] = A[M,K] @ B[N,K]^T  (both operands pre-rounded to tf32)
// MODE 0: QKV  (bias; scatter to q*SCALE / k / v in (wb,h,n,d))
// MODE 1: proj (bias; window-reverse + un-roll; + residual)
// MODE 2: fc1  (bias; exact GELU; output pre-rounded to tf32 for fc2)
// MODE 3: fc2  (bias; + residual)
constexpr int GEMM_SMEM = 65536;   // 2 stages x (16K A + 16K B)

template <int MODE>
__global__ void __launch_bounds__(256, 2) mma_gemm(
    const float* __restrict__ A, const float* __restrict__ B,
    const float* __restrict__ bias, const float* __restrict__ res,
    float* __restrict__ O0, float* __restrict__ O1, float* __restrict__ O2,
    int K, int ldo)
{
    extern __shared__ float dsm[];
    const int t = threadIdx.x;
    const int rowBase = blockIdx.y * 128;
    const int colBase = blockIdx.x * 128;
    const uint32_t sbase = smem_u32(dsm);

    // producer: thread t loads row (t>>1), 16B chunks (t&1)*4 .. +3
    const int pr = t >> 1, ph = t & 1;
    const float* Ap = A + (size_t)(rowBase + pr) * K + ph * 16;
    const float* Bp = B + (size_t)(colBase + pr) * K + ph * 16;
    uint32_t poff[4];
    #pragma unroll
    for (int s = 0; s < 4; s++)
        poff[s] = swz((uint32_t)pr * 128u + (uint32_t)(ph * 4 + s) * 16u);

    const int T = K >> 5;
    #pragma unroll
    for (int p = 0; p < 2; p++) {
        uint32_t sA = sbase + (uint32_t)p * 32768u, sB = sA + 16384u;
        #pragma unroll
        for (int s = 0; s < 4; s++) {
            cp16(sA + poff[s], Ap + p * 32 + s * 4);
            cp16(sB + poff[s], Bp + p * 32 + s * 4);
        }
        cp_commit();
    }

    // consumer: warps 2x4, warp tile 64x32
    const int l = t & 31, w = t >> 5;
    const int wr = w >> 2, wc = w & 3;
    const int ra = l >> 2, ca = l & 3;

    float c[4][4][4];
    #pragma unroll
    for (int mt = 0; mt < 4; mt++)
        #pragma unroll
        for (int nt = 0; nt < 4; nt++)
            #pragma unroll
            for (int j = 0; j < 4; j++) c[mt][nt][j] = 0.f;

    for (int i = 0; i < T; i++) {
        if (i == T - 1) cp_wait<0>(); else cp_wait<1>();
        __syncthreads();
        const float* As = dsm + (i & 1) * 8192;
        const float* Bs = As + 4096;
        #pragma unroll
        for (int kk = 0; kk < 4; kk++) {
            const int k0 = kk * 8;
            uint32_t af[4][4], bf[4][2];
            #pragma unroll
            for (int mt = 0; mt < 4; mt++) {
                int m = wr * 64 + mt * 16 + ra;
                int x = (m & 7) << 2;
                const uint32_t* P  = (const uint32_t*)(As + m * 32);
                const uint32_t* P2 = (const uint32_t*)(As + (m + 8) * 32);
                af[mt][0] = P [(k0 + ca)     ^ x];
                af[mt][1] = P2[(k0 + ca)     ^ x];
                af[mt][2] = P [(k0 + ca + 4) ^ x];
                af[mt][3] = P2[(k0 + ca + 4) ^ x];
            }
            #pragma unroll
            for (int nt = 0; nt < 4; nt++) {
                int n = wc * 32 + nt * 8 + ra;
                int x = (n & 7) << 2;
                const uint32_t* P = (const uint32_t*)(Bs + n * 32);
                bf[nt][0] = P[(k0 + ca)     ^ x];
                bf[nt][1] = P[(k0 + ca + 4) ^ x];
            }
            #pragma unroll
            for (int mt = 0; mt < 4; mt++)
                #pragma unroll
                for (int nt = 0; nt < 4; nt++)
                    mma8(c[mt][nt], af[mt], bf[nt]);
        }
        __syncthreads();
        if (i + 2 < T) {
            uint32_t sA = sbase + (uint32_t)(i & 1) * 32768u, sB = sA + 16384u;
            #pragma unroll
            for (int s = 0; s < 4; s++) {
                cp16(sA + poff[s], Ap + (i + 2) * 32 + s * 4);
                cp16(sB + poff[s], Bp + (i + 2) * 32 + s * 4);
            }
            cp_commit();
        }
    }

    // ---------------- epilogue ----------------
    #pragma unroll
    for (int mt = 0; mt < 4; mt++) {
        #pragma unroll
        for (int rr = 0; rr < 2; rr++) {
            const int gm = rowBase + wr * 64 + mt * 16 + ra + rr * 8;
            int wb = 0, n = 0; size_t orow = 0;
            if (MODE == 0) { wb = gm / 49; n = gm - wb * 49; }
            if (MODE == 1) {
                wb = gm / 49; n = gm - wb * 49;
                int b = wb >> 6; int widx = wb & 63;
                int ii = (widx >> 3) * 7 + n / 7;
                int jj = (widx & 7) * 7 + n % 7;
                int oi = ii + 3; if (oi >= 56) oi -= 56;
                int oj = jj + 3; if (oj >= 56) oj -= 56;
                orow = ((size_t)b * 3136 + oi * 56 + oj) * 256;
            }
            if (MODE == 2 || MODE == 3) orow = (size_t)gm * ldo;

            #pragma unroll
            for (int nt = 0; nt < 4; nt++) {
                const int gc = colBase + wc * 32 + nt * 8 + 2 * ca;
                float2 bb = *(const float2*)(bias + gc);
                float v0 = c[mt][nt][rr * 2 + 0] + bb.x;
                float v1 = c[mt][nt][rr * 2 + 1] + bb.y;

                if (MODE == 0) {
                    int part = gc >> 8;
                    int hh = (gc >> 5) & 7;
                    int dd = gc & 31;
                    float* Op = (part == 0) ? O0 : ((part == 1) ? O1 : O2);
                    if (part == 0) { v0 *= SCALE; v1 *= SCALE; }
                    *(float2*)(Op + (((size_t)wb * 8 + hh) * 49 + n) * 32 + dd)
                        = make_float2(v0, v1);
                } else if (MODE == 1) {
                    float2 rr2 = *(const float2*)(res + orow + gc);
                    *(float2*)(O0 + orow + gc) = make_float2(rr2.x + v0, rr2.y + v1);
                } else if (MODE == 2) {
                    v0 = 0.5f * v0 * (1.0f + erff(v0 * 0.70710678118654752f));
                    v1 = 0.5f * v1 * (1.0f + erff(v1 * 0.70710678118654752f));
                    *(float2*)(O0 + orow + gc) = make_float2(to_tf32(v0), to_tf32(v1));
                } else {
                    float2 rr2 = *(const float2*)(res + orow + gc);
                    *(float2*)(O0 + orow + gc) = make_float2(rr2.x + v0, rr2.y + v1);
                }
            }
        }
    }
}

// ----------------------------------------------------------------------------
extern "C" void kernel_launch(void* const* d_in, const int* in_sizes, int n_in,
                              void* d_out, int out_size)
{
    const float* x      = (const float*)d_in[0];
    const float* mask   = (const float*)d_in[1];
    const float* n1g    = (const float*)d_in[2];
    const float* n1b    = (const float*)d_in[3];
    const float* qkv_w  = (const float*)d_in[4];
    const float* qkv_b  = (const float*)d_in[5];
    const float* relb   = (const float*)d_in[6];
    const float* proj_w = (const float*)d_in[7];
    const float* proj_b = (const float*)d_in[8];
    const float* n2g    = (const float*)d_in[9];
    const float* n2b    = (const float*)d_in[10];
    const float* fc1_w  = (const float*)d_in[11];
    const float* fc1_b  = (const float*)d_in[12];
    const float* fc2_w  = (const float*)d_in[13];
    const float* fc2_b  = (const float*)d_in[14];
    float* out = (float*)d_out;

    float *p_hw, *p_q, *p_k, *p_v, *p_o, *p_x2, *p_h2n, *p_mlp;
    float *p_wqkv, *p_wprj, *p_wfc1, *p_wfc2;
    cudaGetSymbolAddress((void**)&p_hw,   g_hw);
    cudaGetSymbolAddress((void**)&p_q,    g_q);
    cudaGetSymbolAddress((void**)&p_k,    g_k);
    cudaGetSymbolAddress((void**)&p_v,    g_v);
    cudaGetSymbolAddress((void**)&p_o,    g_o);
    cudaGetSymbolAddress((void**)&p_x2,   g_x2);
    cudaGetSymbolAddress((void**)&p_h2n,  g_h2n);
    cudaGetSymbolAddress((void**)&p_mlp,  g_mlp);
    cudaGetSymbolAddress((void**)&p_wqkv, g_wqkv);
    cudaGetSymbolAddress((void**)&p_wprj, g_wprj);
    cudaGetSymbolAddress((void**)&p_wfc1, g_wfc1);
    cudaGetSymbolAddress((void**)&p_wfc2, g_wfc2);

    cudaFuncSetAttribute(mma_gemm<0>, cudaFuncAttributeMaxDynamicSharedMemorySize, GEMM_SMEM);
    cudaFuncSetAttribute(mma_gemm<1>, cudaFuncAttributeMaxDynamicSharedMemorySize, GEMM_SMEM);
    cudaFuncSetAttribute(mma_gemm<2>, cudaFuncAttributeMaxDynamicSharedMemorySize, GEMM_SMEM);
    cudaFuncSetAttribute(mma_gemm<3>, cudaFuncAttributeMaxDynamicSharedMemorySize, GEMM_SMEM);

    // 0. pre-round weights to tf32 (RNA)
    wcvt<<<192, 256>>>((const float4*)qkv_w,  (float4*)p_wqkv, 49152);
    wcvt<<<64,  256>>>((const float4*)proj_w, (float4*)p_wprj, 16384);
    wcvt<<<256, 256>>>((const float4*)fc1_w,  (float4*)p_wfc1, 65536);
    wcvt<<<256, 256>>>((const float4*)fc2_w,  (float4*)p_wfc2, 65536);
    // 1. LN1 + cyclic shift + window partition (tf32-rounded out)
    ln_kernel<<<TOKENS / 8, 256>>>(x, p_hw, n1g, n1b, 1);
    // 2. QKV projection -> q(scaled)/k/v in (wb, h, n, d)
    mma_gemm<0><<<dim3(6, 392), 256, GEMM_SMEM>>>(p_hw, p_wqkv, qkv_b, nullptr,
                                                  p_q, p_k, p_v, 256, 0);
    // 3. Windowed MSA with relative position bias + shift mask
    attn_kernel<<<8192, 256>>>(relb, mask);
    // 4. Output projection + window-reverse + un-roll + residual (x)
    mma_gemm<1><<<dim3(2, 392), 256, GEMM_SMEM>>>(p_o, p_wprj, proj_b, x,
                                                  p_x2, nullptr, nullptr, 256, 256);
    // 5. LN2 (tf32-rounded out)
    ln_kernel<<<TOKENS / 8, 256>>>(p_x2, p_h2n, n2g, n2b, 0);
    // 6. fc1 + GELU (tf32-rounded out)
    mma_gemm<2><<<dim3(8, 392), 256, GEMM_SMEM>>>(p_h2n, p_wfc1, fc1_b, nullptr,
                                                  p_mlp, nullptr, nullptr, 256, 1024);
    // 7. fc2 + residual (x2) -> out
    mma_gemm<3><<<dim3(2, 392), 256, GEMM_SMEM>>>(p_mlp, p_wfc2, fc2_b, p_x2,
                                                  out, nullptr, nullptr, 1024, 256);
}

// round 7
// speedup vs baseline: 3.0231x; 1.1726x over previous
#include <cuda_runtime.h>
#include <cstdint>

#define DEVFN __device__ __forceinline__

constexpr int TOKENS = 16 * 56 * 56;   // 50176
constexpr float SCALE = 0.17677669529663687f;   // 32^-0.5

// Scratch (static device arrays: allocation-free per harness rules)
__device__ float g_hw  [TOKENS * 256];
__device__ float g_q   [TOKENS * 256];
__device__ float g_k   [TOKENS * 256];
__device__ float g_v   [TOKENS * 256];
__device__ float g_o   [TOKENS * 256];
__device__ float g_x2  [TOKENS * 256];
__device__ float g_h2n [TOKENS * 256];
__device__ float g_mlp [TOKENS * 1024];
__device__ float g_wqkv[768 * 256];
__device__ float g_wprj[256 * 256];
__device__ float g_wfc1[1024 * 256];
__device__ float g_wfc2[256 * 1024];

// ------------------------------ PTX helpers ---------------------------------
DEVFN uint32_t smem_u32(const void* p) {
    uint32_t a;
    asm("{ .reg .u64 t; cvta.to.shared.u64 t, %1; cvt.u32.u64 %0, t; }"
        : "=r"(a) : "l"(p));
    return a;
}
DEVFN uint32_t swz(uint32_t o) { return o ^ ((o >> 3) & 0x70u); }
DEVFN void cp16(uint32_t dst, const void* src) {
    asm volatile("cp.async.cg.shared.global [%0], [%1], 16;" :: "r"(dst), "l"(src));
}
DEVFN void cp_commit() { asm volatile("cp.async.commit_group;" ::: "memory"); }
template <int N> DEVFN void cp_wait() {
    asm volatile("cp.async.wait_group %0;" :: "n"(N) : "memory");
}
DEVFN float to_tf32(float x) {
    float r;
    asm("cvt.rna.tf32.f32 %0, %1;" : "=f"(r) : "f"(x));
    return r;
}
DEVFN void mma8(float c[4], const uint32_t a[4], const uint32_t b[2]) {
    asm volatile(
        "mma.sync.aligned.m16n8k8.row.col.f32.tf32.tf32.f32 "
        "{%0,%1,%2,%3}, {%4,%5,%6,%7}, {%8,%9}, {%0,%1,%2,%3};"
        : "+f"(c[0]), "+f"(c[1]), "+f"(c[2]), "+f"(c[3])
        : "r"(a[0]), "r"(a[1]), "r"(a[2]), "r"(a[3]), "r"(b[0]), "r"(b[1]));
}
DEVFN uint32_t f2u(float x) { return __float_as_uint(x); }

// ---------------- all-weights pre-round to tf32 (RNA), single launch ---------
__global__ void __launch_bounds__(256) wcvt_all(
    const float4* __restrict__ w0, const float4* __restrict__ w1,
    const float4* __restrict__ w2, const float4* __restrict__ w3,
    float4* __restrict__ d0, float4* __restrict__ d1,
    float4* __restrict__ d2, float4* __restrict__ d3)
{
    int i = blockIdx.x * 256 + threadIdx.x;
    const float4* s; float4* d; int j;
    if      (i <  49152) { s = w0; d = d0; j = i; }
    else if (i <  65536) { s = w1; d = d1; j = i - 49152; }
    else if (i < 131072) { s = w2; d = d2; j = i - 65536; }
    else                 { s = w3; d = d3; j = i - 131072; }
    float4 v = s[j];
    v.x = to_tf32(v.x); v.y = to_tf32(v.y);
    v.z = to_tf32(v.z); v.w = to_tf32(v.w);
    d[j] = v;
}

// ---------------- LayerNorm (warp/row; outputs pre-rounded to tf32) ----------
__global__ void __launch_bounds__(256) ln_kernel(
    const float* __restrict__ in, float* __restrict__ out,
    const float* __restrict__ gamma, const float* __restrict__ beta,
    int shifted)
{
    int warp = threadIdx.x >> 5, lane = threadIdx.x & 31;
    int t = blockIdx.x * 8 + warp;
    int in_row, out_row;
    if (shifted) {
        int b = t / 3136; int rem = t - b * 3136;
        int i = rem / 56; int j = rem - i * 56;
        int si = i + 3; if (si >= 56) si -= 56;
        int sj = j + 3; if (sj >= 56) sj -= 56;
        in_row = b * 3136 + si * 56 + sj;
        int wb = b * 64 + (i / 7) * 8 + (j / 7);
        int n  = (i % 7) * 7 + (j % 7);
        out_row = wb * 49 + n;
    } else {
        in_row = out_row = t;
    }
    const float4* ip = (const float4*)(in + (size_t)in_row * 256);
    float4 a = ip[lane], b4 = ip[lane + 32];
    float s  = a.x + a.y + a.z + a.w + b4.x + b4.y + b4.z + b4.w;
    float sq = a.x*a.x + a.y*a.y + a.z*a.z + a.w*a.w
             + b4.x*b4.x + b4.y*b4.y + b4.z*b4.z + b4.w*b4.w;
    #pragma unroll
    for (int o = 16; o; o >>= 1) {
        s  += __shfl_xor_sync(0xffffffffu, s,  o);
        sq += __shfl_xor_sync(0xffffffffu, sq, o);
    }
    float mu   = s * (1.0f / 256.0f);
    float var  = sq * (1.0f / 256.0f) - mu * mu;
    float rstd = rsqrtf(var + 1e-5f);
    float4 g0 = ((const float4*)gamma)[lane], g1 = ((const float4*)gamma)[lane + 32];
    float4 e0 = ((const float4*)beta)[lane],  e1 = ((const float4*)beta)[lane + 32];
    float4 o0, o1;
    o0.x = to_tf32((a.x - mu) * rstd * g0.x + e0.x);
    o0.y = to_tf32((a.y - mu) * rstd * g0.y + e0.y);
    o0.z = to_tf32((a.z - mu) * rstd * g0.z + e0.z);
    o0.w = to_tf32((a.w - mu) * rstd * g0.w + e0.w);
    o1.x = to_tf32((b4.x - mu) * rstd * g1.x + e1.x);
    o1.y = to_tf32((b4.y - mu) * rstd * g1.y + e1.y);
    o1.z = to_tf32((b4.z - mu) * rstd * g1.z + e1.z);
    o1.w = to_tf32((b4.w - mu) * rstd * g1.w + e1.w);
    float4* op = (float4*)(out + (size_t)out_row * 256);
    op[lane] = o0; op[lane + 32] = o1;
}

// ---------------- Tensor-core windowed attention -----------------------------
// One block per (window, head): 128 threads / 4 warps.
// QK^T: M=49(pad 64) x N=49(pad 56) x K=32 via m16n8k8 tf32 mma.
// softmax rows in smem (swizzle row-local: reductions unaffected).
// PV: M=49(pad 64) x N=32 x K=49(pad 56, zero-padded).
__global__ void __launch_bounds__(128) attn_mma(
    const float* __restrict__ rel_bias, const float* __restrict__ mask)
{
    int wb = blockIdx.x >> 3;
    int h  = blockIdx.x & 7;
    __shared__ float qs[64 * 32];   // rows m, cols k (stride 32, swizzled)
    __shared__ float ks[56 * 32];   // rows n, cols k
    __shared__ float vt[32 * 64];   // rows dd, cols k (stride 64, swizzled)
    __shared__ float sc[64 * 64];   // rows m, cols n (stride 64, swizzled)

    const int t = threadIdx.x;
    const int l = t & 31, w = t >> 5;
    const int ra = l >> 2, ca = l & 3;
    const int mbase = w * 16;
    size_t base = (size_t)blockIdx.x * (49 * 32);

    // load q/k (rows n, cols d) swizzled; v transposed into vt[dd][n]
    for (int idx = t; idx < 49 * 32; idx += 128) {
        int n = idx >> 5, d = idx & 31;
        uint32_t wi = (uint32_t)(n << 5) + (d ^ ((n & 7) << 2));
        qs[wi] = g_q[base + idx];
        ks[wi] = g_k[base + idx];
        vt[(d << 6) + (n ^ ((d & 7) << 2))] = g_v[base + idx];
    }
    // zero V pad cols 49..55 (blocks NaN/inf leaking through 0*garbage)
    for (int idx = t; idx < 32 * 7; idx += 128) {
        int d = idx / 7, m2 = 49 + idx % 7;
        vt[(d << 6) + (m2 ^ ((d & 7) << 2))] = 0.f;
    }
    __syncthreads();

    // ---- QK^T ----
    float acc[7][4];
    #pragma unroll
    for (int nt = 0; nt < 7; nt++)
        #pragma unroll
        for (int j = 0; j < 4; j++) acc[nt][j] = 0.f;

    const int r0 = mbase + ra, r1 = r0 + 8;
    const int x0 = (r0 & 7) << 2, x1 = (r1 & 7) << 2;
    #pragma unroll
    for (int k0 = 0; k0 < 32; k0 += 8) {
        uint32_t af[4];
        af[0] = f2u(qs[(r0 << 5) + ((k0 + ca)     ^ x0)]);
        af[1] = f2u(qs[(r1 << 5) + ((k0 + ca)     ^ x1)]);
        af[2] = f2u(qs[(r0 << 5) + ((k0 + ca + 4) ^ x0)]);
        af[3] = f2u(qs[(r1 << 5) + ((k0 + ca + 4) ^ x1)]);
        #pragma unroll
        for (int nt = 0; nt < 7; nt++) {
            int n = nt * 8 + ra;
            int xn = (n & 7) << 2;
            uint32_t bf[2];
            bf[0] = f2u(ks[(n << 5) + ((k0 + ca)     ^ xn)]);
            bf[1] = f2u(ks[(n << 5) + ((k0 + ca + 4) ^ xn)]);
            mma8(acc[nt], af, bf);
        }
    }

    // ---- store scores (+rel bias, +mask; -1e30 on pads) ----
    const float* mrow = mask + (size_t)(wb & 63) * 2401;
    #pragma unroll
    for (int nt = 0; nt < 7; nt++) {
        #pragma unroll
        for (int half = 0; half < 2; half++) {
            int row = mbase + ra + half * 8;
            int xr = (row & 7) << 2;
            #pragma unroll
            for (int d2 = 0; d2 < 2; d2++) {
                int col = nt * 8 + 2 * ca + d2;
                float v = -1e30f;
                if (col < 49 && row < 49) {
                    v = acc[nt][half * 2 + d2];
                    int qi = row / 7, qj = row - qi * 7;
                    int ki = col / 7, kj = col - ki * 7;
                    int ridx = (qi - ki + 6) * 13 + (qj - kj + 6);
                    v += rel_bias[ridx * 8 + h] + mrow[row * 49 + col];
                }
                sc[(row << 6) + (col ^ xr)] = v;
            }
        }
    }
    __syncthreads();

    // ---- softmax: warp per row ----
    for (int r = w; r < 49; r += 4) {
        int xr = (r & 7) << 2;
        float* row = sc + (r << 6);
        float v0 = row[l ^ xr];
        float v1 = (l < 24) ? row[(32 + l) ^ xr] : -1e30f;
        float m = fmaxf(v0, v1);
        #pragma unroll
        for (int o = 16; o; o >>= 1) m = fmaxf(m, __shfl_xor_sync(0xffffffffu, m, o));
        float e0 = __expf(v0 - m);
        float e1 = (l < 24) ? __expf(v1 - m) : 0.f;
        float s = e0 + e1;
        #pragma unroll
        for (int o = 16; o; o >>= 1) s += __shfl_xor_sync(0xffffffffu, s, o);
        float inv = 1.0f / s;
        row[l ^ xr] = e0 * inv;
        if (l < 24) row[(32 + l) ^ xr] = e1 * inv;
    }
    __syncthreads();

    // ---- PV ----
    float o[4][4];
    #pragma unroll
    for (int nt = 0; nt < 4; nt++)
        #pragma unroll
        for (int j = 0; j < 4; j++) o[nt][j] = 0.f;

    #pragma unroll
    for (int k0 = 0; k0 < 56; k0 += 8) {
        uint32_t af[4];
        af[0] = f2u(sc[(r0 << 6) + ((k0 + ca)     ^ x0)]);
        af[1] = f2u(sc[(r1 << 6) + ((k0 + ca)     ^ x1)]);
        af[2] = f2u(sc[(r0 << 6) + ((k0 + ca + 4) ^ x0)]);
        af[3] = f2u(sc[(r1 << 6) + ((k0 + ca + 4) ^ x1)]);
        #pragma unroll
        for (int nt = 0; nt < 4; nt++) {
            int n = nt * 8 + ra;
            int xn = (n & 7) << 2;
            uint32_t bf[2];
            bf[0] = f2u(vt[(n << 6) + ((k0 + ca)     ^ xn)]);
            bf[1] = f2u(vt[(n << 6) + ((k0 + ca + 4) ^ xn)]);
            mma8(o[nt], af, bf);
        }
    }

    // ---- store O (tf32-rounded: feeds proj GEMM) ----
    #pragma unroll
    for (int half = 0; half < 2; half++) {
        int row = mbase + ra + half * 8;
        if (row < 49) {
            float* dst = g_o + ((size_t)(wb * 49 + row)) * 256 + h * 32;
            #pragma unroll
            for (int nt = 0; nt < 4; nt++) {
                int col = nt * 8 + 2 * ca;
                *(float2*)(dst + col) = make_float2(
                    to_tf32(o[nt][half * 2 + 0]), to_tf32(o[nt][half * 2 + 1]));
            }
        }
    }
}

// ---------------- tf32 mma.sync GEMM NT, 128x128 tile, 3-stage pipeline ------
// D[M,N] = A[M,K] @ B[N,K]^T  (both operands pre-rounded to tf32)
// MODE 0: QKV  (bias; scatter to q*SCALE / k / v in (wb,h,n,d), tf32-rounded)
// MODE 1: proj (bias; window-reverse + un-roll; + residual)
// MODE 2: fc1  (bias; exact GELU; output pre-rounded to tf32 for fc2)
// MODE 3: fc2  (bias; + residual)
constexpr int GEMM_SMEM = 98304;   // 3 stages x (16K A + 16K B)

template <int MODE>
__global__ void __launch_bounds__(256, 2) mma_gemm(
    const float* __restrict__ A, const float* __restrict__ B,
    const float* __restrict__ bias, const float* __restrict__ res,
    float* __restrict__ O0, float* __restrict__ O1, float* __restrict__ O2,
    int K, int ldo)
{
    extern __shared__ float dsm[];
    const int t = threadIdx.x;
    const int rowBase = blockIdx.y * 128;
    const int colBase = blockIdx.x * 128;
    const uint32_t sbase = smem_u32(dsm);

    // producer: thread t loads row (t>>1), 16B chunks (t&1)*4 .. +3
    const int pr = t >> 1, ph = t & 1;
    const float* Ap = A + (size_t)(rowBase + pr) * K + ph * 16;
    const float* Bp = B + (size_t)(colBase + pr) * K + ph * 16;
    uint32_t poff[4];
    #pragma unroll
    for (int s = 0; s < 4; s++)
        poff[s] = swz((uint32_t)pr * 128u + (uint32_t)(ph * 4 + s) * 16u);

    const int T = K >> 5;
    #pragma unroll
    for (int p = 0; p < 3; p++) {
        uint32_t sA = sbase + (uint32_t)p * 32768u, sB = sA + 16384u;
        #pragma unroll
        for (int s = 0; s < 4; s++) {
            cp16(sA + poff[s], Ap + p * 32 + s * 4);
            cp16(sB + poff[s], Bp + p * 32 + s * 4);
        }
        cp_commit();
    }

    // consumer: warps 2x4, warp tile 64x32
    const int l = t & 31, w = t >> 5;
    const int wr = w >> 2, wc = w & 3;
    const int ra = l >> 2, ca = l & 3;

    float c[4][4][4];
    #pragma unroll
    for (int mt = 0; mt < 4; mt++)
        #pragma unroll
        for (int nt = 0; nt < 4; nt++)
            #pragma unroll
            for (int j = 0; j < 4; j++) c[mt][nt][j] = 0.f;

    int stage = 0;
    for (int i = 0; i < T; i++) {
        if (i <= T - 3)      cp_wait<2>();
        else if (i == T - 2) cp_wait<1>();
        else                 cp_wait<0>();
        __syncthreads();
        const float* As = dsm + stage * 8192;
        const float* Bs = As + 4096;
        #pragma unroll
        for (int kk = 0; kk < 4; kk++) {
            const int k0 = kk * 8;
            uint32_t af[4][4], bf[4][2];
            #pragma unroll
            for (int mt = 0; mt < 4; mt++) {
                int m = wr * 64 + mt * 16 + ra;
                int x = (m & 7) << 2;
                const uint32_t* P  = (const uint32_t*)(As + m * 32);
                const uint32_t* P2 = (const uint32_t*)(As + (m + 8) * 32);
                af[mt][0] = P [(k0 + ca)     ^ x];
                af[mt][1] = P2[(k0 + ca)     ^ x];
                af[mt][2] = P [(k0 + ca + 4) ^ x];
                af[mt][3] = P2[(k0 + ca + 4) ^ x];
            }
            #pragma unroll
            for (int nt = 0; nt < 4; nt++) {
                int n = wc * 32 + nt * 8 + ra;
                int x = (n & 7) << 2;
                const uint32_t* P = (const uint32_t*)(Bs + n * 32);
                bf[nt][0] = P[(k0 + ca)     ^ x];
                bf[nt][1] = P[(k0 + ca + 4) ^ x];
            }
            #pragma unroll
            for (int mt = 0; mt < 4; mt++)
                #pragma unroll
                for (int nt = 0; nt < 4; nt++)
                    mma8(c[mt][nt], af[mt], bf[nt]);
        }
        __syncthreads();
        if (i + 3 < T) {
            uint32_t sA = sbase + (uint32_t)stage * 32768u, sB = sA + 16384u;
            #pragma unroll
            for (int s = 0; s < 4; s++) {
                cp16(sA + poff[s], Ap + (i + 3) * 32 + s * 4);
                cp16(sB + poff[s], Bp + (i + 3) * 32 + s * 4);
            }
            cp_commit();
        }
        stage = (stage == 2) ? 0 : stage + 1;
    }

    // ---------------- epilogue ----------------
    #pragma unroll
    for (int mt = 0; mt < 4; mt++) {
        #pragma unroll
        for (int rr = 0; rr < 2; rr++) {
            const int gm = rowBase + wr * 64 + mt * 16 + ra + rr * 8;
            int wb = 0, n = 0; size_t orow = 0;
            if (MODE == 0) { wb = gm / 49; n = gm - wb * 49; }
            if (MODE == 1) {
                wb = gm / 49; n = gm - wb * 49;
                int b = wb >> 6; int widx = wb & 63;
                int ii = (widx >> 3) * 7 + n / 7;
                int jj = (widx & 7) * 7 + n % 7;
                int oi = ii + 3; if (oi >= 56) oi -= 56;
                int oj = jj + 3; if (oj >= 56) oj -= 56;
                orow = ((size_t)b * 3136 + oi * 56 + oj) * 256;
            }
            if (MODE == 2 || MODE == 3) orow = (size_t)gm * ldo;

            #pragma unroll
            for (int nt = 0; nt < 4; nt++) {
                const int gc = colBase + wc * 32 + nt * 8 + 2 * ca;
                float2 bb = *(const float2*)(bias + gc);
                float v0 = c[mt][nt][rr * 2 + 0] + bb.x;
                float v1 = c[mt][nt][rr * 2 + 1] + bb.y;

                if (MODE == 0) {
                    int part = gc >> 8;
                    int hh = (gc >> 5) & 7;
                    int dd = gc & 31;
                    float* Op = (part == 0) ? O0 : ((part == 1) ? O1 : O2);
                    if (part == 0) { v0 *= SCALE; v1 *= SCALE; }
                    *(float2*)(Op + (((size_t)wb * 8 + hh) * 49 + n) * 32 + dd)
                        = make_float2(to_tf32(v0), to_tf32(v1));
                } else if (MODE == 1) {
                    float2 rr2 = *(const float2*)(res + orow + gc);
                    *(float2*)(O0 + orow + gc) = make_float2(rr2.x + v0, rr2.y + v1);
                } else if (MODE == 2) {
                    v0 = 0.5f * v0 * (1.0f + erff(v0 * 0.70710678118654752f));
                    v1 = 0.5f * v1 * (1.0f + erff(v1 * 0.70710678118654752f));
                    *(float2*)(O0 + orow + gc) = make_float2(to_tf32(v0), to_tf32(v1));
                } else {
                    float2 rr2 = *(const float2*)(res + orow + gc);
                    *(float2*)(O0 + orow + gc) = make_float2(rr2.x + v0, rr2.y + v1);
                }
            }
        }
    }
}

// ----------------------------------------------------------------------------
extern "C" void kernel_launch(void* const* d_in, const int* in_sizes, int n_in,
                              void* d_out, int out_size)
{
    const float* x      = (const float*)d_in[0];
    const float* mask   = (const float*)d_in[1];
    const float* n1g    = (const float*)d_in[2];
    const float* n1b    = (const float*)d_in[3];
    const float* qkv_w  = (const float*)d_in[4];
    const float* qkv_b  = (const float*)d_in[5];
    const float* relb   = (const float*)d_in[6];
    const float* proj_w = (const float*)d_in[7];
    const float* proj_b = (const float*)d_in[8];
    const float* n2g    = (const float*)d_in[9];
    const float* n2b    = (const float*)d_in[10];
    const float* fc1_w  = (const float*)d_in[11];
    const float* fc1_b  = (const float*)d_in[12];
    const float* fc2_w  = (const float*)d_in[13];
    const float* fc2_b  = (const float*)d_in[14];
    float* out = (float*)d_out;

    float *p_hw, *p_q, *p_k, *p_v, *p_o, *p_x2, *p_h2n, *p_mlp;
    float *p_wqkv, *p_wprj, *p_wfc1, *p_wfc2;
    cudaGetSymbolAddress((void**)&p_hw,   g_hw);
    cudaGetSymbolAddress((void**)&p_q,    g_q);
    cudaGetSymbolAddress((void**)&p_k,    g_k);
    cudaGetSymbolAddress((void**)&p_v,    g_v);
    cudaGetSymbolAddress((void**)&p_o,    g_o);
    cudaGetSymbolAddress((void**)&p_x2,   g_x2);
    cudaGetSymbolAddress((void**)&p_h2n,  g_h2n);
    cudaGetSymbolAddress((void**)&p_mlp,  g_mlp);
    cudaGetSymbolAddress((void**)&p_wqkv, g_wqkv);
    cudaGetSymbolAddress((void**)&p_wprj, g_wprj);
    cudaGetSymbolAddress((void**)&p_wfc1, g_wfc1);
    cudaGetSymbolAddress((void**)&p_wfc2, g_wfc2);

    cudaFuncSetAttribute(mma_gemm<0>, cudaFuncAttributeMaxDynamicSharedMemorySize, GEMM_SMEM);
    cudaFuncSetAttribute(mma_gemm<1>, cudaFuncAttributeMaxDynamicSharedMemorySize, GEMM_SMEM);
    cudaFuncSetAttribute(mma_gemm<2>, cudaFuncAttributeMaxDynamicSharedMemorySize, GEMM_SMEM);
    cudaFuncSetAttribute(mma_gemm<3>, cudaFuncAttributeMaxDynamicSharedMemorySize, GEMM_SMEM);

    // 0. pre-round all weights to tf32 (one launch)
    wcvt_all<<<768, 256>>>((const float4*)qkv_w, (const float4*)proj_w,
                           (const float4*)fc1_w, (const float4*)fc2_w,
                           (float4*)p_wqkv, (float4*)p_wprj,
                           (float4*)p_wfc1, (float4*)p_wfc2);
    // 1. LN1 + cyclic shift + window partition (tf32-rounded out)
    ln_kernel<<<TOKENS / 8, 256>>>(x, p_hw, n1g, n1b, 1);
    // 2. QKV projection -> q(scaled)/k/v in (wb, h, n, d), tf32-rounded
    mma_gemm<0><<<dim3(6, 392), 256, GEMM_SMEM>>>(p_hw, p_wqkv, qkv_b, nullptr,
                                                  p_q, p_k, p_v, 256, 0);
    // 3. Windowed MSA (tensor-core) with relative position bias + shift mask
    attn_mma<<<8192, 128>>>(relb, mask);
    // 4. Output projection + window-reverse + un-roll + residual (x)
    mma_gemm<1><<<dim3(2, 392), 256, GEMM_SMEM>>>(p_o, p_wprj, proj_b, x,
                                                  p_x2, nullptr, nullptr, 256, 256);
    // 5. LN2 (tf32-rounded out)
    ln_kernel<<<TOKENS / 8, 256>>>(p_x2, p_h2n, n2g, n2b, 0);
    // 6. fc1 + GELU (tf32-rounded out)
    mma_gemm<2><<<dim3(8, 392), 256, GEMM_SMEM>>>(p_h2n, p_wfc1, fc1_b, nullptr,
                                                  p_mlp, nullptr, nullptr, 256, 1024);
    // 7. fc2 + residual (x2) -> out
    mma_gemm<3><<<dim3(2, 392), 256, GEMM_SMEM>>>(p_mlp, p_wfc2, fc2_b, p_x2,
                                                  out, nullptr, nullptr, 1024, 256);
}

// round 8
// speedup vs baseline: 3.3254x; 1.1000x over previous
#include <cuda_runtime.h>
#include <cstdint>

#define DEVFN __device__ __forceinline__

constexpr int TOKENS = 16 * 56 * 56;   // 50176
constexpr float SCALE = 0.17677669529663687f;   // 32^-0.5

// Scratch (static device arrays: allocation-free per harness rules)
__device__ float g_hw  [TOKENS * 256];
__device__ float g_q   [TOKENS * 256];
__device__ float g_k   [TOKENS * 256];
__device__ float g_v   [TOKENS * 256];
__device__ float g_o   [TOKENS * 256];
__device__ float g_x2  [TOKENS * 256];
__device__ float g_h2n [TOKENS * 256];
__device__ float g_mlp [TOKENS * 1024];
__device__ float g_wqkv[768 * 256];
__device__ float g_wprj[256 * 256];
__device__ float g_wfc1[1024 * 256];
__device__ float g_wfc2[256 * 1024];
__device__ float g_btile[512 * 49 * 56];   // fused rel_bias+mask, pads=-1e30

// ------------------------------ PTX helpers ---------------------------------
DEVFN uint32_t smem_u32(const void* p) {
    uint32_t a;
    asm("{ .reg .u64 t; cvta.to.shared.u64 t, %1; cvt.u32.u64 %0, t; }"
        : "=r"(a) : "l"(p));
    return a;
}
DEVFN uint32_t swz(uint32_t o) { return o ^ ((o >> 3) & 0x70u); }
DEVFN void cp16(uint32_t dst, const void* src) {
    asm volatile("cp.async.cg.shared.global [%0], [%1], 16;" :: "r"(dst), "l"(src));
}
DEVFN void cp_commit() { asm volatile("cp.async.commit_group;" ::: "memory"); }
template <int N> DEVFN void cp_wait() {
    asm volatile("cp.async.wait_group %0;" :: "n"(N) : "memory");
}
DEVFN float to_tf32(float x) {
    float r;
    asm("cvt.rna.tf32.f32 %0, %1;" : "=f"(r) : "f"(x));
    return r;
}
DEVFN void mma8(float c[4], const uint32_t a[4], const uint32_t b[2]) {
    asm volatile(
        "mma.sync.aligned.m16n8k8.row.col.f32.tf32.tf32.f32 "
        "{%0,%1,%2,%3}, {%4,%5,%6,%7}, {%8,%9}, {%0,%1,%2,%3};"
        : "+f"(c[0]), "+f"(c[1]), "+f"(c[2]), "+f"(c[3])
        : "r"(a[0]), "r"(a[1]), "r"(a[2]), "r"(a[3]), "r"(b[0]), "r"(b[1]));
}
DEVFN uint32_t f2u(float x) { return __float_as_uint(x); }

// ---------------- all-weights pre-round to tf32 (RNA), single launch ---------
__global__ void __launch_bounds__(256) wcvt_all(
    const float4* __restrict__ w0, const float4* __restrict__ w1,
    const float4* __restrict__ w2, const float4* __restrict__ w3,
    float4* __restrict__ d0, float4* __restrict__ d1,
    float4* __restrict__ d2, float4* __restrict__ d3)
{
    int i = blockIdx.x * 256 + threadIdx.x;
    const float4* s; float4* d; int j;
    if      (i <  49152) { s = w0; d = d0; j = i; }
    else if (i <  65536) { s = w1; d = d1; j = i - 49152; }
    else if (i < 131072) { s = w2; d = d2; j = i - 65536; }
    else                 { s = w3; d = d3; j = i - 131072; }
    float4 v = s[j];
    v.x = to_tf32(v.x); v.y = to_tf32(v.y);
    v.z = to_tf32(v.z); v.w = to_tf32(v.w);
    d[j] = v;
}

// ---------------- fused attention bias tiles ---------------------------------
// btile[h*64+widx][row][col] = rel_bias[relidx(row,col)*8+h] + mask[widx][row][col]
// cols 49..55 = -1e30 (softmax pad).
__global__ void __launch_bounds__(256) bias_prep(
    const float* __restrict__ rel_bias, const float* __restrict__ mask,
    float* __restrict__ btile)
{
    int h = blockIdx.x >> 6;
    int widx = blockIdx.x & 63;
    float* dst = btile + (size_t)blockIdx.x * (49 * 56);
    const float* mrow = mask + (size_t)widx * 2401;
    for (int e = threadIdx.x; e < 49 * 56; e += 256) {
        int row = e / 56, col = e - row * 56;
        float v = -1e30f;
        if (col < 49) {
            int qi = row / 7, qj = row - qi * 7;
            int ki = col / 7, kj = col - ki * 7;
            int ridx = (qi - ki + 6) * 13 + (qj - kj + 6);
            v = rel_bias[ridx * 8 + h] + mrow[row * 49 + col];
        }
        dst[e] = v;
    }
}

// ---------------- LayerNorm (warp/row; outputs pre-rounded to tf32) ----------
__global__ void __launch_bounds__(256) ln_kernel(
    const float* __restrict__ in, float* __restrict__ out,
    const float* __restrict__ gamma, const float* __restrict__ beta,
    int shifted)
{
    int warp = threadIdx.x >> 5, lane = threadIdx.x & 31;
    int t = blockIdx.x * 8 + warp;
    int in_row, out_row;
    if (shifted) {
        int b = t / 3136; int rem = t - b * 3136;
        int i = rem / 56; int j = rem - i * 56;
        int si = i + 3; if (si >= 56) si -= 56;
        int sj = j + 3; if (sj >= 56) sj -= 56;
        in_row = b * 3136 + si * 56 + sj;
        int wb = b * 64 + (i / 7) * 8 + (j / 7);
        int n  = (i % 7) * 7 + (j % 7);
        out_row = wb * 49 + n;
    } else {
        in_row = out_row = t;
    }
    const float4* ip = (const float4*)(in + (size_t)in_row * 256);
    float4 a = ip[lane], b4 = ip[lane + 32];
    float s  = a.x + a.y + a.z + a.w + b4.x + b4.y + b4.z + b4.w;
    float sq = a.x*a.x + a.y*a.y + a.z*a.z + a.w*a.w
             + b4.x*b4.x + b4.y*b4.y + b4.z*b4.z + b4.w*b4.w;
    #pragma unroll
    for (int o = 16; o; o >>= 1) {
        s  += __shfl_xor_sync(0xffffffffu, s,  o);
        sq += __shfl_xor_sync(0xffffffffu, sq, o);
    }
    float mu   = s * (1.0f / 256.0f);
    float var  = sq * (1.0f / 256.0f) - mu * mu;
    float rstd = rsqrtf(var + 1e-5f);
    float4 g0 = ((const float4*)gamma)[lane], g1 = ((const float4*)gamma)[lane + 32];
    float4 e0 = ((const float4*)beta)[lane],  e1 = ((const float4*)beta)[lane + 32];
    float4 o0, o1;
    o0.x = to_tf32((a.x - mu) * rstd * g0.x + e0.x);
    o0.y = to_tf32((a.y - mu) * rstd * g0.y + e0.y);
    o0.z = to_tf32((a.z - mu) * rstd * g0.z + e0.z);
    o0.w = to_tf32((a.w - mu) * rstd * g0.w + e0.w);
    o1.x = to_tf32((b4.x - mu) * rstd * g1.x + e1.x);
    o1.y = to_tf32((b4.y - mu) * rstd * g1.y + e1.y);
    o1.z = to_tf32((b4.z - mu) * rstd * g1.z + e1.z);
    o1.w = to_tf32((b4.w - mu) * rstd * g1.w + e1.w);
    float4* op = (float4*)(out + (size_t)out_row * 256);
    op[lane] = o0; op[lane + 32] = o1;
}

// ---------------- Tensor-core windowed attention -----------------------------
// One block per (window, head): 128 threads / 4 warps.
// QK^T (M pad 64, N pad 56, K=32) -> bias from precomputed btile ->
// register softmax (rows live in 4-lane groups) -> P to smem -> PV.
__global__ void __launch_bounds__(128) attn_mma(const float* __restrict__ btile)
{
    int wb = blockIdx.x >> 3;
    int h  = blockIdx.x & 7;
    __shared__ float qs[64 * 32];   // rows m, cols k (swizzled)
    __shared__ float ks[56 * 32];   // rows n, cols k (swizzled; pad rows zeroed)
    __shared__ float vt[32 * 64];   // rows d,  cols n (swizzled; pad cols zeroed)
    __shared__ float sc[64 * 64];   // P: rows m, cols n (swizzled)

    const int t = threadIdx.x;
    const int l = t & 31, w = t >> 5;
    const int ra = l >> 2, ca = l & 3;
    const int mbase = w * 16;
    size_t base = (size_t)blockIdx.x * (49 * 32);
    const float* bt = btile + (size_t)(h * 64 + (wb & 63)) * (49 * 56);

    // vectorized loads: q/k float4->STS.128 (swizzle XOR has no bits<2), v transposed
    for (int idx = t; idx < 392; idx += 128) {
        int n = idx >> 3, d4 = (idx & 7) << 2;
        uint32_t wi = (uint32_t)(n << 5) + (d4 ^ ((n & 7) << 2));
        *(float4*)(qs + wi) = *(const float4*)(g_q + base + (n << 5) + d4);
        *(float4*)(ks + wi) = *(const float4*)(g_k + base + (n << 5) + d4);
        float4 vv = *(const float4*)(g_v + base + (n << 5) + d4);
        vt[((d4 + 0) << 6) + (n ^ (((d4 + 0) & 7) << 2))] = vv.x;
        vt[((d4 + 1) << 6) + (n ^ (((d4 + 1) & 7) << 2))] = vv.y;
        vt[((d4 + 2) << 6) + (n ^ (((d4 + 2) & 7) << 2))] = vv.z;
        vt[((d4 + 3) << 6) + (n ^ (((d4 + 3) & 7) << 2))] = vv.w;
    }
    // zero ks pad rows 49..55 (NaN garbage would survive the bias add)
    for (int idx = t; idx < 56; idx += 128) {
        int row = 49 + (idx >> 3), d4 = (idx & 7) << 2;
        *(float4*)(ks + (row << 5) + (d4 ^ ((row & 7) << 2))) =
            make_float4(0.f, 0.f, 0.f, 0.f);
    }
    // zero vt pad cols 49..55
    for (int idx = t; idx < 224; idx += 128) {
        int d = idx / 7, m2 = 49 + idx - d * 7;
        vt[(d << 6) + (m2 ^ ((d & 7) << 2))] = 0.f;
    }
    __syncthreads();

    const int r0 = mbase + ra, r1 = r0 + 8;
    const int x0 = (r0 & 7) << 2, x1 = (r1 & 7) << 2;

    // ---- QK^T ----
    float acc[7][4];
    #pragma unroll
    for (int nt = 0; nt < 7; nt++)
        #pragma unroll
        for (int j = 0; j < 4; j++) acc[nt][j] = 0.f;

    #pragma unroll
    for (int k0 = 0; k0 < 32; k0 += 8) {
        uint32_t af[4];
        af[0] = f2u(qs[(r0 << 5) + ((k0 + ca)     ^ x0)]);
        af[1] = f2u(qs[(r1 << 5) + ((k0 + ca)     ^ x1)]);
        af[2] = f2u(qs[(r0 << 5) + ((k0 + ca + 4) ^ x0)]);
        af[3] = f2u(qs[(r1 << 5) + ((k0 + ca + 4) ^ x1)]);
        #pragma unroll
        for (int nt = 0; nt < 7; nt++) {
            int n = nt * 8 + ra;
            int xn = (n & 7) << 2;
            uint32_t bf[2];
            bf[0] = f2u(ks[(n << 5) + ((k0 + ca)     ^ xn)]);
            bf[1] = f2u(ks[(n << 5) + ((k0 + ca + 4) ^ xn)]);
            mma8(acc[nt], af, bf);
        }
    }

    // ---- fused bias (coalesced float2 from btile; -1e30 guard on pad rows) ----
    #pragma unroll
    for (int nt = 0; nt < 7; nt++) {
        int cb = nt * 8 + 2 * ca;
        if (r0 < 49) {
            float2 b0 = *(const float2*)(bt + r0 * 56 + cb);
            acc[nt][0] += b0.x; acc[nt][1] += b0.y;
        } else { acc[nt][0] = -1e30f; acc[nt][1] = -1e30f; }
        if (r1 < 49) {
            float2 b1 = *(const float2*)(bt + r1 * 56 + cb);
            acc[nt][2] += b1.x; acc[nt][3] += b1.y;
        } else { acc[nt][2] = -1e30f; acc[nt][3] = -1e30f; }
    }

    // ---- register softmax: each row lives in a 4-lane group (shfl xor 1,2) ----
    float m0 = -1e30f, m1 = -1e30f;
    #pragma unroll
    for (int nt = 0; nt < 7; nt++) {
        m0 = fmaxf(m0, fmaxf(acc[nt][0], acc[nt][1]));
        m1 = fmaxf(m1, fmaxf(acc[nt][2], acc[nt][3]));
    }
    m0 = fmaxf(m0, __shfl_xor_sync(0xffffffffu, m0, 1));
    m0 = fmaxf(m0, __shfl_xor_sync(0xffffffffu, m0, 2));
    m1 = fmaxf(m1, __shfl_xor_sync(0xffffffffu, m1, 1));
    m1 = fmaxf(m1, __shfl_xor_sync(0xffffffffu, m1, 2));
    float s0 = 0.f, s1 = 0.f;
    #pragma unroll
    for (int nt = 0; nt < 7; nt++) {
        acc[nt][0] = __expf(acc[nt][0] - m0); s0 += acc[nt][0];
        acc[nt][1] = __expf(acc[nt][1] - m0); s0 += acc[nt][1];
        acc[nt][2] = __expf(acc[nt][2] - m1); s1 += acc[nt][2];
        acc[nt][3] = __expf(acc[nt][3] - m1); s1 += acc[nt][3];
    }
    s0 += __shfl_xor_sync(0xffffffffu, s0, 1);
    s0 += __shfl_xor_sync(0xffffffffu, s0, 2);
    s1 += __shfl_xor_sync(0xffffffffu, s1, 1);
    s1 += __shfl_xor_sync(0xffffffffu, s1, 2);
    float i0 = 1.0f / s0, i1 = 1.0f / s1;

    // ---- store normalized P (STS.64, swizzled) ----
    #pragma unroll
    for (int nt = 0; nt < 7; nt++) {
        int cb = nt * 8 + 2 * ca;
        *(float2*)(sc + (r0 << 6) + (cb ^ x0)) =
            make_float2(acc[nt][0] * i0, acc[nt][1] * i0);
        *(float2*)(sc + (r1 << 6) + (cb ^ x1)) =
            make_float2(acc[nt][2] * i1, acc[nt][3] * i1);
    }
    __syncthreads();

    // ---- PV ----
    float o[4][4];
    #pragma unroll
    for (int nt = 0; nt < 4; nt++)
        #pragma unroll
        for (int j = 0; j < 4; j++) o[nt][j] = 0.f;

    #pragma unroll
    for (int k0 = 0; k0 < 56; k0 += 8) {
        uint32_t af[4];
        af[0] = f2u(sc[(r0 << 6) + ((k0 + ca)     ^ x0)]);
        af[1] = f2u(sc[(r1 << 6) + ((k0 + ca)     ^ x1)]);
        af[2] = f2u(sc[(r0 << 6) + ((k0 + ca + 4) ^ x0)]);
        af[3] = f2u(sc[(r1 << 6) + ((k0 + ca + 4) ^ x1)]);
        #pragma unroll
        for (int nt = 0; nt < 4; nt++) {
            int n = nt * 8 + ra;
            int xn = (n & 7) << 2;
            uint32_t bf[2];
            bf[0] = f2u(vt[(n << 6) + ((k0 + ca)     ^ xn)]);
            bf[1] = f2u(vt[(n << 6) + ((k0 + ca + 4) ^ xn)]);
            mma8(o[nt], af, bf);
        }
    }

    // ---- store O (tf32-rounded: feeds proj GEMM) ----
    #pragma unroll
    for (int half = 0; half < 2; half++) {
        int row = mbase + ra + half * 8;
        if (row < 49) {
            float* dst = g_o + ((size_t)(wb * 49 + row)) * 256 + h * 32;
            #pragma unroll
            for (int nt = 0; nt < 4; nt++) {
                int col = nt * 8 + 2 * ca;
                *(float2*)(dst + col) = make_float2(
                    to_tf32(o[nt][half * 2 + 0]), to_tf32(o[nt][half * 2 + 1]));
            }
        }
    }
}

// ---------------- tf32 mma.sync GEMM NT, 128x128 tile, 3-stage pipeline ------
// D[M,N] = A[M,K] @ B[N,K]^T  (both operands pre-rounded to tf32)
// MODE 0: QKV  (bias; scatter to q*SCALE / k / v in (wb,h,n,d), tf32-rounded)
// MODE 1: proj (bias; window-reverse + un-roll; + residual)
// MODE 2: fc1  (bias; exact GELU; output pre-rounded to tf32 for fc2)
// MODE 3: fc2  (bias; + residual)
constexpr int GEMM_SMEM = 98304;   // 3 stages x (16K A + 16K B)

template <int MODE>
__global__ void __launch_bounds__(256, 2) mma_gemm(
    const float* __restrict__ A, const float* __restrict__ B,
    const float* __restrict__ bias, const float* __restrict__ res,
    float* __restrict__ O0, float* __restrict__ O1, float* __restrict__ O2,
    int K, int ldo)
{
    extern __shared__ float dsm[];
    const int t = threadIdx.x;
    const int rowBase = blockIdx.y * 128;
    const int colBase = blockIdx.x * 128;
    const uint32_t sbase = smem_u32(dsm);

    // producer: thread t loads row (t>>1), 16B chunks (t&1)*4 .. +3
    const int pr = t >> 1, ph = t & 1;
    const float* Ap = A + (size_t)(rowBase + pr) * K + ph * 16;
    const float* Bp = B + (size_t)(colBase + pr) * K + ph * 16;
    uint32_t poff[4];
    #pragma unroll
    for (int s = 0; s < 4; s++)
        poff[s] = swz((uint32_t)pr * 128u + (uint32_t)(ph * 4 + s) * 16u);

    const int T = K >> 5;
    #pragma unroll
    for (int p = 0; p < 3; p++) {
        uint32_t sA = sbase + (uint32_t)p * 32768u, sB = sA + 16384u;
        #pragma unroll
        for (int s = 0; s < 4; s++) {
            cp16(sA + poff[s], Ap + p * 32 + s * 4);
            cp16(sB + poff[s], Bp + p * 32 + s * 4);
        }
        cp_commit();
    }

    // consumer: warps 2x4, warp tile 64x32
    const int l = t & 31, w = t >> 5;
    const int wr = w >> 2, wc = w & 3;
    const int ra = l >> 2, ca = l & 3;

    float c[4][4][4];
    #pragma unroll
    for (int mt = 0; mt < 4; mt++)
        #pragma unroll
        for (int nt = 0; nt < 4; nt++)
            #pragma unroll
            for (int j = 0; j < 4; j++) c[mt][nt][j] = 0.f;

    int stage = 0;
    for (int i = 0; i < T; i++) {
        if (i <= T - 3)      cp_wait<2>();
        else if (i == T - 2) cp_wait<1>();
        else                 cp_wait<0>();
        __syncthreads();
        const float* As = dsm + stage * 8192;
        const float* Bs = As + 4096;
        #pragma unroll
        for (int kk = 0; kk < 4; kk++) {
            const int k0 = kk * 8;
            uint32_t af[4][4], bf[4][2];
            #pragma unroll
            for (int mt = 0; mt < 4; mt++) {
                int m = wr * 64 + mt * 16 + ra;
                int x = (m & 7) << 2;
                const uint32_t* P  = (const uint32_t*)(As + m * 32);
                const uint32_t* P2 = (const uint32_t*)(As + (m + 8) * 32);
                af[mt][0] = P [(k0 + ca)     ^ x];
                af[mt][1] = P2[(k0 + ca)     ^ x];
                af[mt][2] = P [(k0 + ca + 4) ^ x];
                af[mt][3] = P2[(k0 + ca + 4) ^ x];
            }
            #pragma unroll
            for (int nt = 0; nt < 4; nt++) {
                int n = wc * 32 + nt * 8 + ra;
                int x = (n & 7) << 2;
                const uint32_t* P = (const uint32_t*)(Bs + n * 32);
                bf[nt][0] = P[(k0 + ca)     ^ x];
                bf[nt][1] = P[(k0 + ca + 4) ^ x];
            }
            #pragma unroll
            for (int mt = 0; mt < 4; mt++)
                #pragma unroll
                for (int nt = 0; nt < 4; nt++)
                    mma8(c[mt][nt], af[mt], bf[nt]);
        }
        __syncthreads();
        if (i + 3 < T) {
            uint32_t sA = sbase + (uint32_t)stage * 32768u, sB = sA + 16384u;
            #pragma unroll
            for (int s = 0; s < 4; s++) {
                cp16(sA + poff[s], Ap + (i + 3) * 32 + s * 4);
                cp16(sB + poff[s], Bp + (i + 3) * 32 + s * 4);
            }
            cp_commit();
        }
        stage = (stage == 2) ? 0 : stage + 1;
    }

    // ---------------- epilogue ----------------
    #pragma unroll
    for (int mt = 0; mt < 4; mt++) {
        #pragma unroll
        for (int rr = 0; rr < 2; rr++) {
            const int gm = rowBase + wr * 64 + mt * 16 + ra + rr * 8;
            int wb = 0, n = 0; size_t orow = 0;
            if (MODE == 0) { wb = gm / 49; n = gm - wb * 49; }
            if (MODE == 1) {
                wb = gm / 49; n = gm - wb * 49;
                int b = wb >> 6; int widx = wb & 63;
                int ii = (widx >> 3) * 7 + n / 7;
                int jj = (widx & 7) * 7 + n % 7;
                int oi = ii + 3; if (oi >= 56) oi -= 56;
                int oj = jj + 3; if (oj >= 56) oj -= 56;
                orow = ((size_t)b * 3136 + oi * 56 + oj) * 256;
            }
            if (MODE == 2 || MODE == 3) orow = (size_t)gm * ldo;

            #pragma unroll
            for (int nt = 0; nt < 4; nt++) {
                const int gc = colBase + wc * 32 + nt * 8 + 2 * ca;
                float2 bb = *(const float2*)(bias + gc);
                float v0 = c[mt][nt][rr * 2 + 0] + bb.x;
                float v1 = c[mt][nt][rr * 2 + 1] + bb.y;

                if (MODE == 0) {
                    int part = gc >> 8;
                    int hh = (gc >> 5) & 7;
                    int dd = gc & 31;
                    float* Op = (part == 0) ? O0 : ((part == 1) ? O1 : O2);
                    if (part == 0) { v0 *= SCALE; v1 *= SCALE; }
                    *(float2*)(Op + (((size_t)wb * 8 + hh) * 49 + n) * 32 + dd)
                        = make_float2(to_tf32(v0), to_tf32(v1));
                } else if (MODE == 1) {
                    float2 rr2 = *(const float2*)(res + orow + gc);
                    *(float2*)(O0 + orow + gc) = make_float2(rr2.x + v0, rr2.y + v1);
                } else if (MODE == 2) {
                    v0 = 0.5f * v0 * (1.0f + erff(v0 * 0.70710678118654752f));
                    v1 = 0.5f * v1 * (1.0f + erff(v1 * 0.70710678118654752f));
                    *(float2*)(O0 + orow + gc) = make_float2(to_tf32(v0), to_tf32(v1));
                } else {
                    float2 rr2 = *(const float2*)(res + orow + gc);
                    *(float2*)(O0 + orow + gc) = make_float2(rr2.x + v0, rr2.y + v1);
                }
            }
        }
    }
}

// ----------------------------------------------------------------------------
extern "C" void kernel_launch(void* const* d_in, const int* in_sizes, int n_in,
                              void* d_out, int out_size)
{
    const float* x      = (const float*)d_in[0];
    const float* mask   = (const float*)d_in[1];
    const float* n1g    = (const float*)d_in[2];
    const float* n1b    = (const float*)d_in[3];
    const float* qkv_w  = (const float*)d_in[4];
    const float* qkv_b  = (const float*)d_in[5];
    const float* relb   = (const float*)d_in[6];
    const float* proj_w = (const float*)d_in[7];
    const float* proj_b = (const float*)d_in[8];
    const float* n2g    = (const float*)d_in[9];
    const float* n2b    = (const float*)d_in[10];
    const float* fc1_w  = (const float*)d_in[11];
    const float* fc1_b  = (const float*)d_in[12];
    const float* fc2_w  = (const float*)d_in[13];
    const float* fc2_b  = (const float*)d_in[14];
    float* out = (float*)d_out;

    float *p_hw, *p_q, *p_k, *p_v, *p_o, *p_x2, *p_h2n, *p_mlp;
    float *p_wqkv, *p_wprj, *p_wfc1, *p_wfc2, *p_btile;
    cudaGetSymbolAddress((void**)&p_hw,    g_hw);
    cudaGetSymbolAddress((void**)&p_q,     g_q);
    cudaGetSymbolAddress((void**)&p_k,     g_k);
    cudaGetSymbolAddress((void**)&p_v,     g_v);
    cudaGetSymbolAddress((void**)&p_o,     g_o);
    cudaGetSymbolAddress((void**)&p_x2,    g_x2);
    cudaGetSymbolAddress((void**)&p_h2n,   g_h2n);
    cudaGetSymbolAddress((void**)&p_mlp,   g_mlp);
    cudaGetSymbolAddress((void**)&p_wqkv,  g_wqkv);
    cudaGetSymbolAddress((void**)&p_wprj,  g_wprj);
    cudaGetSymbolAddress((void**)&p_wfc1,  g_wfc1);
    cudaGetSymbolAddress((void**)&p_wfc2,  g_wfc2);
    cudaGetSymbolAddress((void**)&p_btile, g_btile);

    cudaFuncSetAttribute(mma_gemm<0>, cudaFuncAttributeMaxDynamicSharedMemorySize, GEMM_SMEM);
    cudaFuncSetAttribute(mma_gemm<1>, cudaFuncAttributeMaxDynamicSharedMemorySize, GEMM_SMEM);
    cudaFuncSetAttribute(mma_gemm<2>, cudaFuncAttributeMaxDynamicSharedMemorySize, GEMM_SMEM);
    cudaFuncSetAttribute(mma_gemm<3>, cudaFuncAttributeMaxDynamicSharedMemorySize, GEMM_SMEM);

    // 0. pre-round all weights to tf32; precompute fused attention bias tiles
    wcvt_all<<<768, 256>>>((const float4*)qkv_w, (const float4*)proj_w,
                           (const float4*)fc1_w, (const float4*)fc2_w,
                           (float4*)p_wqkv, (float4*)p_wprj,
                           (float4*)p_wfc1, (float4*)p_wfc2);
    bias_prep<<<512, 256>>>(relb, mask, p_btile);
    // 1. LN1 + cyclic shift + window partition (tf32-rounded out)
    ln_kernel<<<TOKENS / 8, 256>>>(x, p_hw, n1g, n1b, 1);
    // 2. QKV projection -> q(scaled)/k/v in (wb, h, n, d), tf32-rounded
    mma_gemm<0><<<dim3(6, 392), 256, GEMM_SMEM>>>(p_hw, p_wqkv, qkv_b, nullptr,
                                                  p_q, p_k, p_v, 256, 0);
    // 3. Windowed MSA (tensor-core) with fused bias tiles
    attn_mma<<<8192, 128>>>(p_btile);
    // 4. Output projection + window-reverse + un-roll + residual (x)
    mma_gemm<1><<<dim3(2, 392), 256, GEMM_SMEM>>>(p_o, p_wprj, proj_b, x,
                                                  p_x2, nullptr, nullptr, 256, 256);
    // 5. LN2 (tf32-rounded out)
    ln_kernel<<<TOKENS / 8, 256>>>(p_x2, p_h2n, n2g, n2b, 0);
    // 6. fc1 + GELU (tf32-rounded out)
    mma_gemm<2><<<dim3(8, 392), 256, GEMM_SMEM>>>(p_h2n, p_wfc1, fc1_b, nullptr,
                                                  p_mlp, nullptr, nullptr, 256, 1024);
    // 7. fc2 + residual (x2) -> out
    mma_gemm<3><<<dim3(2, 392), 256, GEMM_SMEM>>>(p_mlp, p_wfc2, fc2_b, p_x2,
                                                  out, nullptr, nullptr, 1024, 256);
}

// round 9
// speedup vs baseline: 3.4060x; 1.0242x over previous
#include <cuda_runtime.h>
#include <cstdint>

#define DEVFN __device__ __forceinline__

constexpr int TOKENS = 16 * 56 * 56;   // 50176
constexpr float SCALE = 0.17677669529663687f;   // 32^-0.5

// Scratch (static device arrays: allocation-free per harness rules)
__device__ float g_hw  [TOKENS * 256];
__device__ float g_q   [TOKENS * 256];
__device__ float g_k   [TOKENS * 256];
__device__ float g_v   [TOKENS * 256];
__device__ float g_o   [TOKENS * 256];
__device__ float g_x2  [TOKENS * 256];
__device__ float g_h2n [TOKENS * 256];
__device__ float g_mlp [TOKENS * 1024];
__device__ float g_wqkv[768 * 256];
__device__ float g_wprj[256 * 256];
__device__ float g_wfc1[1024 * 256];
__device__ float g_wfc2[256 * 1024];
__device__ float g_btile[512 * 49 * 56];   // fused rel_bias+mask, pads=-1e30

// ------------------------------ PTX helpers ---------------------------------
DEVFN uint32_t smem_u32(const void* p) {
    uint32_t a;
    asm("{ .reg .u64 t; cvta.to.shared.u64 t, %1; cvt.u32.u64 %0, t; }"
        : "=r"(a) : "l"(p));
    return a;
}
DEVFN uint32_t swz(uint32_t o) { return o ^ ((o >> 3) & 0x70u); }
DEVFN void cp16(uint32_t dst, const void* src) {
    asm volatile("cp.async.cg.shared.global [%0], [%1], 16;" :: "r"(dst), "l"(src));
}
DEVFN void cp_commit() { asm volatile("cp.async.commit_group;" ::: "memory"); }
template <int N> DEVFN void cp_wait() {
    asm volatile("cp.async.wait_group %0;" :: "n"(N) : "memory");
}
DEVFN float to_tf32(float x) {
    float r;
    asm("cvt.rna.tf32.f32 %0, %1;" : "=f"(r) : "f"(x));
    return r;
}
DEVFN void mma8(float c[4], const uint32_t a[4], const uint32_t b[2]) {
    asm volatile(
        "mma.sync.aligned.m16n8k8.row.col.f32.tf32.tf32.f32 "
        "{%0,%1,%2,%3}, {%4,%5,%6,%7}, {%8,%9}, {%0,%1,%2,%3};"
        : "+f"(c[0]), "+f"(c[1]), "+f"(c[2]), "+f"(c[3])
        : "r"(a[0]), "r"(a[1]), "r"(a[2]), "r"(a[3]), "r"(b[0]), "r"(b[1]));
}
DEVFN uint32_t f2u(float x) { return __float_as_uint(x); }

// ---------------- all-weights pre-round to tf32 (RNA), single launch ---------
__global__ void __launch_bounds__(256) wcvt_all(
    const float4* __restrict__ w0, const float4* __restrict__ w1,
    const float4* __restrict__ w2, const float4* __restrict__ w3,
    float4* __restrict__ d0, float4* __restrict__ d1,
    float4* __restrict__ d2, float4* __restrict__ d3)
{
    int i = blockIdx.x * 256 + threadIdx.x;
    const float4* s; float4* d; int j;
    if      (i <  49152) { s = w0; d = d0; j = i; }
    else if (i <  65536) { s = w1; d = d1; j = i - 49152; }
    else if (i < 131072) { s = w2; d = d2; j = i - 65536; }
    else                 { s = w3; d = d3; j = i - 131072; }
    float4 v = s[j];
    v.x = to_tf32(v.x); v.y = to_tf32(v.y);
    v.z = to_tf32(v.z); v.w = to_tf32(v.w);
    d[j] = v;
}

// ---------------- fused attention bias tiles ---------------------------------
__global__ void __launch_bounds__(256) bias_prep(
    const float* __restrict__ rel_bias, const float* __restrict__ mask,
    float* __restrict__ btile)
{
    int h = blockIdx.x >> 6;
    int widx = blockIdx.x & 63;
    float* dst = btile + (size_t)blockIdx.x * (49 * 56);
    const float* mrow = mask + (size_t)widx * 2401;
    for (int e = threadIdx.x; e < 49 * 56; e += 256) {
        int row = e / 56, col = e - row * 56;
        float v = -1e30f;
        if (col < 49) {
            int qi = row / 7, qj = row - qi * 7;
            int ki = col / 7, kj = col - ki * 7;
            int ridx = (qi - ki + 6) * 13 + (qj - kj + 6);
            v = rel_bias[ridx * 8 + h] + mrow[row * 49 + col];
        }
        dst[e] = v;
    }
}

// ---------------- LayerNorm (warp/row; outputs pre-rounded to tf32) ----------
__global__ void __launch_bounds__(256) ln_kernel(
    const float* __restrict__ in, float* __restrict__ out,
    const float* __restrict__ gamma, const float* __restrict__ beta,
    int shifted)
{
    int warp = threadIdx.x >> 5, lane = threadIdx.x & 31;
    int t = blockIdx.x * 8 + warp;
    int in_row, out_row;
    if (shifted) {
        int b = t / 3136; int rem = t - b * 3136;
        int i = rem / 56; int j = rem - i * 56;
        int si = i + 3; if (si >= 56) si -= 56;
        int sj = j + 3; if (sj >= 56) sj -= 56;
        in_row = b * 3136 + si * 56 + sj;
        int wb = b * 64 + (i / 7) * 8 + (j / 7);
        int n  = (i % 7) * 7 + (j % 7);
        out_row = wb * 49 + n;
    } else {
        in_row = out_row = t;
    }
    const float4* ip = (const float4*)(in + (size_t)in_row * 256);
    float4 a = ip[lane], b4 = ip[lane + 32];
    float s  = a.x + a.y + a.z + a.w + b4.x + b4.y + b4.z + b4.w;
    float sq = a.x*a.x + a.y*a.y + a.z*a.z + a.w*a.w
             + b4.x*b4.x + b4.y*b4.y + b4.z*b4.z + b4.w*b4.w;
    #pragma unroll
    for (int o = 16; o; o >>= 1) {
        s  += __shfl_xor_sync(0xffffffffu, s,  o);
        sq += __shfl_xor_sync(0xffffffffu, sq, o);
    }
    float mu   = s * (1.0f / 256.0f);
    float var  = sq * (1.0f / 256.0f) - mu * mu;
    float rstd = rsqrtf(var + 1e-5f);
    float4 g0 = ((const float4*)gamma)[lane], g1 = ((const float4*)gamma)[lane + 32];
    float4 e0 = ((const float4*)beta)[lane],  e1 = ((const float4*)beta)[lane + 32];
    float4 o0, o1;
    o0.x = to_tf32((a.x - mu) * rstd * g0.x + e0.x);
    o0.y = to_tf32((a.y - mu) * rstd * g0.y + e0.y);
    o0.z = to_tf32((a.z - mu) * rstd * g0.z + e0.z);
    o0.w = to_tf32((a.w - mu) * rstd * g0.w + e0.w);
    o1.x = to_tf32((b4.x - mu) * rstd * g1.x + e1.x);
    o1.y = to_tf32((b4.y - mu) * rstd * g1.y + e1.y);
    o1.z = to_tf32((b4.z - mu) * rstd * g1.z + e1.z);
    o1.w = to_tf32((b4.w - mu) * rstd * g1.w + e1.w);
    float4* op = (float4*)(out + (size_t)out_row * 256);
    op[lane] = o0; op[lane + 32] = o1;
}

// ---------------- Tensor-core windowed attention -----------------------------
// One block per (window, head): 128 threads / 4 warps. 24KB smem:
// sc (P, 16KB) overlays qs+ks (dead after QK^T). vt separate.
__global__ void __launch_bounds__(128, 6) attn_mma(const float* __restrict__ btile)
{
    int wb = blockIdx.x >> 3;
    int h  = blockIdx.x & 7;
    __shared__ float smem[6144];    // 24KB
    float* qs = smem;               // [64*32]  rows m, cols k (swizzled)
    float* ks = smem + 2048;        // [56*32]  rows n, cols k (pad rows zeroed)
    float* vt = smem + 4096;        // [32*64]  rows d, cols n (pad cols zeroed)
    float* sc = smem;               // [64*64]  P, overlays qs+ks

    const int t = threadIdx.x;
    const int l = t & 31, w = t >> 5;
    const int ra = l >> 2, ca = l & 3;
    const int mbase = w * 16;
    size_t base = (size_t)blockIdx.x * (49 * 32);
    const float* bt = btile + (size_t)(h * 64 + (wb & 63)) * (49 * 56);

    for (int idx = t; idx < 392; idx += 128) {
        int n = idx >> 3, d4 = (idx & 7) << 2;
        uint32_t wi = (uint32_t)(n << 5) + (d4 ^ ((n & 7) << 2));
        *(float4*)(qs + wi) = *(const float4*)(g_q + base + (n << 5) + d4);
        *(float4*)(ks + wi) = *(const float4*)(g_k + base + (n << 5) + d4);
        float4 vv = *(const float4*)(g_v + base + (n << 5) + d4);
        vt[((d4 + 0) << 6) + (n ^ (((d4 + 0) & 7) << 2))] = vv.x;
        vt[((d4 + 1) << 6) + (n ^ (((d4 + 1) & 7) << 2))] = vv.y;
        vt[((d4 + 2) << 6) + (n ^ (((d4 + 2) & 7) << 2))] = vv.z;
        vt[((d4 + 3) << 6) + (n ^ (((d4 + 3) & 7) << 2))] = vv.w;
    }
    // zero ks pad rows 49..55 (garbage would survive the bias add)
    for (int idx = t; idx < 56; idx += 128) {
        int row = 49 + (idx >> 3), d4 = (idx & 7) << 2;
        *(float4*)(ks + (row << 5) + (d4 ^ ((row & 7) << 2))) =
            make_float4(0.f, 0.f, 0.f, 0.f);
    }
    // zero vt pad cols 49..55
    for (int idx = t; idx < 224; idx += 128) {
        int d = idx / 7, m2 = 49 + idx - d * 7;
        vt[(d << 6) + (m2 ^ ((d & 7) << 2))] = 0.f;
    }
    __syncthreads();

    const int r0 = mbase + ra, r1 = r0 + 8;
    const int x0 = (r0 & 7) << 2, x1 = (r1 & 7) << 2;

    // ---- QK^T ----
    float acc[7][4];
    #pragma unroll
    for (int nt = 0; nt < 7; nt++)
        #pragma unroll
        for (int j = 0; j < 4; j++) acc[nt][j] = 0.f;

    #pragma unroll
    for (int k0 = 0; k0 < 32; k0 += 8) {
        uint32_t af[4];
        af[0] = f2u(qs[(r0 << 5) + ((k0 + ca)     ^ x0)]);
        af[1] = f2u(qs[(r1 << 5) + ((k0 + ca)     ^ x1)]);
        af[2] = f2u(qs[(r0 << 5) + ((k0 + ca + 4) ^ x0)]);
        af[3] = f2u(qs[(r1 << 5) + ((k0 + ca + 4) ^ x1)]);
        #pragma unroll
        for (int nt = 0; nt < 7; nt++) {
            int n = nt * 8 + ra;
            int xn = (n & 7) << 2;
            uint32_t bf[2];
            bf[0] = f2u(ks[(n << 5) + ((k0 + ca)     ^ xn)]);
            bf[1] = f2u(ks[(n << 5) + ((k0 + ca + 4) ^ xn)]);
            mma8(acc[nt], af, bf);
        }
    }

    // ---- fused bias (coalesced float2; -1e30 on pad rows) ----
    #pragma unroll
    for (int nt = 0; nt < 7; nt++) {
        int cb = nt * 8 + 2 * ca;
        if (r0 < 49) {
            float2 b0 = *(const float2*)(bt + r0 * 56 + cb);
            acc[nt][0] += b0.x; acc[nt][1] += b0.y;
        } else { acc[nt][0] = -1e30f; acc[nt][1] = -1e30f; }
        if (r1 < 49) {
            float2 b1 = *(const float2*)(bt + r1 * 56 + cb);
            acc[nt][2] += b1.x; acc[nt][3] += b1.y;
        } else { acc[nt][2] = -1e30f; acc[nt][3] = -1e30f; }
    }

    // ---- register softmax (rows in 4-lane groups) ----
    float m0 = -1e30f, m1 = -1e30f;
    #pragma unroll
    for (int nt = 0; nt < 7; nt++) {
        m0 = fmaxf(m0, fmaxf(acc[nt][0], acc[nt][1]));
        m1 = fmaxf(m1, fmaxf(acc[nt][2], acc[nt][3]));
    }
    m0 = fmaxf(m0, __shfl_xor_sync(0xffffffffu, m0, 1));
    m0 = fmaxf(m0, __shfl_xor_sync(0xffffffffu, m0, 2));
    m1 = fmaxf(m1, __shfl_xor_sync(0xffffffffu, m1, 1));
    m1 = fmaxf(m1, __shfl_xor_sync(0xffffffffu, m1, 2));
    float s0 = 0.f, s1 = 0.f;
    #pragma unroll
    for (int nt = 0; nt < 7; nt++) {
        acc[nt][0] = __expf(acc[nt][0] - m0); s0 += acc[nt][0];
        acc[nt][1] = __expf(acc[nt][1] - m0); s0 += acc[nt][1];
        acc[nt][2] = __expf(acc[nt][2] - m1); s1 += acc[nt][2];
        acc[nt][3] = __expf(acc[nt][3] - m1); s1 += acc[nt][3];
    }
    s0 += __shfl_xor_sync(0xffffffffu, s0, 1);
    s0 += __shfl_xor_sync(0xffffffffu, s0, 2);
    s1 += __shfl_xor_sync(0xffffffffu, s1, 1);
    s1 += __shfl_xor_sync(0xffffffffu, s1, 2);
    float i0 = 1.0f / s0, i1 = 1.0f / s1;

    // all warps done reading qs/ks before sc overlays them
    __syncthreads();

    // ---- store normalized P (STS.64, swizzled) ----
    #pragma unroll
    for (int nt = 0; nt < 7; nt++) {
        int cb = nt * 8 + 2 * ca;
        *(float2*)(sc + (r0 << 6) + (cb ^ x0)) =
            make_float2(acc[nt][0] * i0, acc[nt][1] * i0);
        *(float2*)(sc + (r1 << 6) + (cb ^ x1)) =
            make_float2(acc[nt][2] * i1, acc[nt][3] * i1);
    }
    __syncthreads();

    // ---- PV ----
    float o[4][4];
    #pragma unroll
    for (int nt = 0; nt < 4; nt++)
        #pragma unroll
        for (int j = 0; j < 4; j++) o[nt][j] = 0.f;

    #pragma unroll
    for (int k0 = 0; k0 < 56; k0 += 8) {
        uint32_t af[4];
        af[0] = f2u(sc[(r0 << 6) + ((k0 + ca)     ^ x0)]);
        af[1] = f2u(sc[(r1 << 6) + ((k0 + ca)     ^ x1)]);
        af[2] = f2u(sc[(r0 << 6) + ((k0 + ca + 4) ^ x0)]);
        af[3] = f2u(sc[(r1 << 6) + ((k0 + ca + 4) ^ x1)]);
        #pragma unroll
        for (int nt = 0; nt < 4; nt++) {
            int n = nt * 8 + ra;
            int xn = (n & 7) << 2;
            uint32_t bf[2];
            bf[0] = f2u(vt[(n << 6) + ((k0 + ca)     ^ xn)]);
            bf[1] = f2u(vt[(n << 6) + ((k0 + ca + 4) ^ xn)]);
            mma8(o[nt], af, bf);
        }
    }

    // ---- store O (tf32-rounded: feeds proj GEMM) ----
    #pragma unroll
    for (int half = 0; half < 2; half++) {
        int row = mbase + ra + half * 8;
        if (row < 49) {
            float* dst = g_o + ((size_t)(wb * 49 + row)) * 256 + h * 32;
            #pragma unroll
            for (int nt = 0; nt < 4; nt++) {
                int col = nt * 8 + 2 * ca;
                *(float2*)(dst + col) = make_float2(
                    to_tf32(o[nt][half * 2 + 0]), to_tf32(o[nt][half * 2 + 1]));
            }
        }
    }
}

// ---------------- tf32 mma.sync GEMM NT, 128x128 tile, 3-stage, 1 sync/iter --
// Prefetch chunk i+2 -> stage (i+2)%3 == (i-1)%3, issued AFTER the top barrier
// (which proves all warps finished computing stage (i-1)%3). One commit per
// iteration (possibly empty) keeps wait_group<1> == "chunk i arrived".
constexpr int GEMM_SMEM = 98304;   // 3 stages x (16K A + 16K B)

template <int MODE>
__global__ void __launch_bounds__(256, 2) mma_gemm(
    const float* __restrict__ A, const float* __restrict__ B,
    const float* __restrict__ bias, const float* __restrict__ res,
    float* __restrict__ O0, float* __restrict__ O1, float* __restrict__ O2,
    int K, int ldo)
{
    extern __shared__ float dsm[];
    const int t = threadIdx.x;
    const int rowBase = blockIdx.y * 128;
    const int colBase = blockIdx.x * 128;
    const uint32_t sbase = smem_u32(dsm);

    const int pr = t >> 1, ph = t & 1;
    const float* Ap = A + (size_t)(rowBase + pr) * K + ph * 16;
    const float* Bp = B + (size_t)(colBase + pr) * K + ph * 16;
    uint32_t poff[4];
    #pragma unroll
    for (int s = 0; s < 4; s++)
        poff[s] = swz((uint32_t)pr * 128u + (uint32_t)(ph * 4 + s) * 16u);

    const int T = K >> 5;
    #pragma unroll
    for (int p = 0; p < 2; p++) {
        uint32_t sA = sbase + (uint32_t)p * 32768u, sB = sA + 16384u;
        #pragma unroll
        for (int s = 0; s < 4; s++) {
            cp16(sA + poff[s], Ap + p * 32 + s * 4);
            cp16(sB + poff[s], Bp + p * 32 + s * 4);
        }
        cp_commit();
    }

    const int l = t & 31, w = t >> 5;
    const int wr = w >> 2, wc = w & 3;
    const int ra = l >> 2, ca = l & 3;

    float c[4][4][4];
    #pragma unroll
    for (int mt = 0; mt < 4; mt++)
        #pragma unroll
        for (int nt = 0; nt < 4; nt++)
            #pragma unroll
            for (int j = 0; j < 4; j++) c[mt][nt][j] = 0.f;

    int stage = 0;
    for (int i = 0; i < T; i++) {
        cp_wait<1>();
        __syncthreads();
        // prefetch chunk i+2 into stage (i+2)%3 (its readers finished at iter i-1)
        if (i + 2 < T) {
            int ws = stage + 2; if (ws >= 3) ws -= 3;
            uint32_t sA = sbase + (uint32_t)ws * 32768u, sB = sA + 16384u;
            #pragma unroll
            for (int s = 0; s < 4; s++) {
                cp16(sA + poff[s], Ap + (i + 2) * 32 + s * 4);
                cp16(sB + poff[s], Bp + (i + 2) * 32 + s * 4);
            }
        }
        cp_commit();   // always: keeps group-count invariant for wait<1>

        const float* As = dsm + stage * 8192;
        const float* Bs = As + 4096;
        #pragma unroll
        for (int kk = 0; kk < 4; kk++) {
            const int k0 = kk * 8;
            uint32_t af[4][4], bf[4][2];
            #pragma unroll
            for (int mt = 0; mt < 4; mt++) {
                int m = wr * 64 + mt * 16 + ra;
                int x = (m & 7) << 2;
                const uint32_t* P  = (const uint32_t*)(As + m * 32);
                const uint32_t* P2 = (const uint32_t*)(As + (m + 8) * 32);
                af[mt][0] = P [(k0 + ca)     ^ x];
                af[mt][1] = P2[(k0 + ca)     ^ x];
                af[mt][2] = P [(k0 + ca + 4) ^ x];
                af[mt][3] = P2[(k0 + ca + 4) ^ x];
            }
            #pragma unroll
            for (int nt = 0; nt < 4; nt++) {
                int n = wc * 32 + nt * 8 + ra;
                int x = (n & 7) << 2;
                const uint32_t* P = (const uint32_t*)(Bs + n * 32);
                bf[nt][0] = P[(k0 + ca)     ^ x];
                bf[nt][1] = P[(k0 + ca + 4) ^ x];
            }
            #pragma unroll
            for (int mt = 0; mt < 4; mt++)
                #pragma unroll
                for (int nt = 0; nt < 4; nt++)
                    mma8(c[mt][nt], af[mt], bf[nt]);
        }
        stage = (stage == 2) ? 0 : stage + 1;
    }

    // ---------------- epilogue ----------------
    #pragma unroll
    for (int mt = 0; mt < 4; mt++) {
        #pragma unroll
        for (int rr = 0; rr < 2; rr++) {
            const int gm = rowBase + wr * 64 + mt * 16 + ra + rr * 8;
            int wb = 0, n = 0; size_t orow = 0;
            if (MODE == 0) { wb = gm / 49; n = gm - wb * 49; }
            if (MODE == 1) {
                wb = gm / 49; n = gm - wb * 49;
                int b = wb >> 6; int widx = wb & 63;
                int ii = (widx >> 3) * 7 + n / 7;
                int jj = (widx & 7) * 7 + n % 7;
                int oi = ii + 3; if (oi >= 56) oi -= 56;
                int oj = jj + 3; if (oj >= 56) oj -= 56;
                orow = ((size_t)b * 3136 + oi * 56 + oj) * 256;
            }
            if (MODE == 2 || MODE == 3) orow = (size_t)gm * ldo;

            #pragma unroll
            for (int nt = 0; nt < 4; nt++) {
                const int gc = colBase + wc * 32 + nt * 8 + 2 * ca;
                float2 bb = *(const float2*)(bias + gc);
                float v0 = c[mt][nt][rr * 2 + 0] + bb.x;
                float v1 = c[mt][nt][rr * 2 + 1] + bb.y;

                if (MODE == 0) {
                    int part = gc >> 8;
                    int hh = (gc >> 5) & 7;
                    int dd = gc & 31;
                    float* Op = (part == 0) ? O0 : ((part == 1) ? O1 : O2);
                    if (part == 0) { v0 *= SCALE; v1 *= SCALE; }
                    *(float2*)(Op + (((size_t)wb * 8 + hh) * 49 + n) * 32 + dd)
                        = make_float2(to_tf32(v0), to_tf32(v1));
                } else if (MODE == 1) {
                    float2 rr2 = *(const float2*)(res + orow + gc);
                    *(float2*)(O0 + orow + gc) = make_float2(rr2.x + v0, rr2.y + v1);
                } else if (MODE == 2) {
                    v0 = 0.5f * v0 * (1.0f + erff(v0 * 0.70710678118654752f));
                    v1 = 0.5f * v1 * (1.0f + erff(v1 * 0.70710678118654752f));
                    *(float2*)(O0 + orow + gc) = make_float2(to_tf32(v0), to_tf32(v1));
                } else {
                    float2 rr2 = *(const float2*)(res + orow + gc);
                    *(float2*)(O0 + orow + gc) = make_float2(rr2.x + v0, rr2.y + v1);
                }
            }
        }
    }
}

// ----------------------------------------------------------------------------
extern "C" void kernel_launch(void* const* d_in, const int* in_sizes, int n_in,
                              void* d_out, int out_size)
{
    const float* x      = (const float*)d_in[0];
    const float* mask   = (const float*)d_in[1];
    const float* n1g    = (const float*)d_in[2];
    const float* n1b    = (const float*)d_in[3];
    const float* qkv_w  = (const float*)d_in[4];
    const float* qkv_b  = (const float*)d_in[5];
    const float* relb   = (const float*)d_in[6];
    const float* proj_w = (const float*)d_in[7];
    const float* proj_b = (const float*)d_in[8];
    const float* n2g    = (const float*)d_in[9];
    const float* n2b    = (const float*)d_in[10];
    const float* fc1_w  = (const float*)d_in[11];
    const float* fc1_b  = (const float*)d_in[12];
    const float* fc2_w  = (const float*)d_in[13];
    const float* fc2_b  = (const float*)d_in[14];
    float* out = (float*)d_out;

    float *p_hw, *p_q, *p_k, *p_v, *p_o, *p_x2, *p_h2n, *p_mlp;
    float *p_wqkv, *p_wprj, *p_wfc1, *p_wfc2, *p_btile;
    cudaGetSymbolAddress((void**)&p_hw,    g_hw);
    cudaGetSymbolAddress((void**)&p_q,     g_q);
    cudaGetSymbolAddress((void**)&p_k,     g_k);
    cudaGetSymbolAddress((void**)&p_v,     g_v);
    cudaGetSymbolAddress((void**)&p_o,     g_o);
    cudaGetSymbolAddress((void**)&p_x2,    g_x2);
    cudaGetSymbolAddress((void**)&p_h2n,   g_h2n);
    cudaGetSymbolAddress((void**)&p_mlp,   g_mlp);
    cudaGetSymbolAddress((void**)&p_wqkv,  g_wqkv);
    cudaGetSymbolAddress((void**)&p_wprj,  g_wprj);
    cudaGetSymbolAddress((void**)&p_wfc1,  g_wfc1);
    cudaGetSymbolAddress((void**)&p_wfc2,  g_wfc2);
    cudaGetSymbolAddress((void**)&p_btile, g_btile);

    cudaFuncSetAttribute(mma_gemm<0>, cudaFuncAttributeMaxDynamicSharedMemorySize, GEMM_SMEM);
    cudaFuncSetAttribute(mma_gemm<1>, cudaFuncAttributeMaxDynamicSharedMemorySize, GEMM_SMEM);
    cudaFuncSetAttribute(mma_gemm<2>, cudaFuncAttributeMaxDynamicSharedMemorySize, GEMM_SMEM);
    cudaFuncSetAttribute(mma_gemm<3>, cudaFuncAttributeMaxDynamicSharedMemorySize, GEMM_SMEM);

    wcvt_all<<<768, 256>>>((const float4*)qkv_w, (const float4*)proj_w,
                           (const float4*)fc1_w, (const float4*)fc2_w,
                           (float4*)p_wqkv, (float4*)p_wprj,
                           (float4*)p_wfc1, (float4*)p_wfc2);
    bias_prep<<<512, 256>>>(relb, mask, p_btile);
    ln_kernel<<<TOKENS / 8, 256>>>(x, p_hw, n1g, n1b, 1);
    mma_gemm<0><<<dim3(6, 392), 256, GEMM_SMEM>>>(p_hw, p_wqkv, qkv_b, nullptr,
                                                  p_q, p_k, p_v, 256, 0);
    attn_mma<<<8192, 128>>>(p_btile);
    mma_gemm<1><<<dim3(2, 392), 256, GEMM_SMEM>>>(p_o, p_wprj, proj_b, x,
                                                  p_x2, nullptr, nullptr, 256, 256);
    ln_kernel<<<TOKENS / 8, 256>>>(p_x2, p_h2n, n2g, n2b, 0);
    mma_gemm<2><<<dim3(8, 392), 256, GEMM_SMEM>>>(p_h2n, p_wfc1, fc1_b, nullptr,
                                                  p_mlp, nullptr, nullptr, 256, 1024);
    mma_gemm<3><<<dim3(2, 392), 256, GEMM_SMEM>>>(p_mlp, p_wfc2, fc2_b, p_x2,
                                                  out, nullptr, nullptr, 1024, 256);
}

// round 10
// speedup vs baseline: 5.2268x; 1.5346x over previous
#include <cuda_runtime.h>
#include <cuda_bf16.h>
#include <cstdint>

#define DEVFN __device__ __forceinline__

constexpr int TOKENS = 16 * 56 * 56;   // 50176
constexpr float SCALE = 0.17677669529663687f;   // 32^-0.5

// Scratch (static device arrays: allocation-free per harness rules)
__device__ float g_q   [TOKENS * 256];
__device__ float g_k   [TOKENS * 256];
__device__ float g_v   [TOKENS * 256];
__device__ float g_x2  [TOKENS * 256];
__device__ float g_btile[512 * 49 * 56];            // fused rel_bias+mask
__device__ __nv_bfloat16 g_hw_bf [TOKENS * 256];    // LN1 out (windowed)
__device__ __nv_bfloat16 g_o_bf  [TOKENS * 256];    // attention out
__device__ __nv_bfloat16 g_h2n_bf[TOKENS * 256];    // LN2 out
__device__ __nv_bfloat16 g_mlp_bf[TOKENS * 1024];   // fc1+gelu out
__device__ __nv_bfloat16 g_wqkv_bf[768 * 256];
__device__ __nv_bfloat16 g_wprj_bf[256 * 256];
__device__ __nv_bfloat16 g_wfc1_bf[1024 * 256];
__device__ __nv_bfloat16 g_wfc2_bf[256 * 1024];

// ------------------------------ PTX helpers ---------------------------------
DEVFN uint32_t smem_u32(const void* p) {
    uint32_t a;
    asm("{ .reg .u64 t; cvta.to.shared.u64 t, %1; cvt.u32.u64 %0, t; }"
        : "=r"(a) : "l"(p));
    return a;
}
DEVFN uint32_t swz(uint32_t o) { return o ^ ((o >> 3) & 0x70u); }
DEVFN void cp16(uint32_t dst, const void* src) {
    asm volatile("cp.async.cg.shared.global [%0], [%1], 16;" :: "r"(dst), "l"(src));
}
DEVFN void cp_commit() { asm volatile("cp.async.commit_group;" ::: "memory"); }
template <int N> DEVFN void cp_wait() {
    asm volatile("cp.async.wait_group %0;" :: "n"(N) : "memory");
}
DEVFN float to_tf32(float x) {
    float r;
    asm("cvt.rna.tf32.f32 %0, %1;" : "=f"(r) : "f"(x));
    return r;
}
DEVFN uint32_t bfp(float a, float b) {   // pack 2 floats -> bf16x2 (RNE)
    __nv_bfloat162 t = __floats2bfloat162_rn(a, b);
    return *(uint32_t*)&t;
}
// tf32 mma (attention)
DEVFN void mma8(float c[4], const uint32_t a[4], const uint32_t b[2]) {
    asm volatile(
        "mma.sync.aligned.m16n8k8.row.col.f32.tf32.tf32.f32 "
        "{%0,%1,%2,%3}, {%4,%5,%6,%7}, {%8,%9}, {%0,%1,%2,%3};"
        : "+f"(c[0]), "+f"(c[1]), "+f"(c[2]), "+f"(c[3])
        : "r"(a[0]), "r"(a[1]), "r"(a[2]), "r"(a[3]), "r"(b[0]), "r"(b[1]));
}
// bf16 mma (GEMMs): K=16 per instruction
DEVFN void mma16(float c[4], const uint32_t a[4], const uint32_t b[2]) {
    asm volatile(
        "mma.sync.aligned.m16n8k16.row.col.f32.bf16.bf16.f32 "
        "{%0,%1,%2,%3}, {%4,%5,%6,%7}, {%8,%9}, {%0,%1,%2,%3};"
        : "+f"(c[0]), "+f"(c[1]), "+f"(c[2]), "+f"(c[3])
        : "r"(a[0]), "r"(a[1]), "r"(a[2]), "r"(a[3]), "r"(b[0]), "r"(b[1]));
}
DEVFN uint32_t f2u(float x) { return __float_as_uint(x); }

// ---------------- all-weights f32 -> bf16 (RNE), single launch ---------------
__global__ void __launch_bounds__(256) wcvt_all(
    const float4* __restrict__ w0, const float4* __restrict__ w1,
    const float4* __restrict__ w2, const float4* __restrict__ w3,
    uint2* __restrict__ d0, uint2* __restrict__ d1,
    uint2* __restrict__ d2, uint2* __restrict__ d3)
{
    int i = blockIdx.x * 256 + threadIdx.x;
    const float4* s; uint2* d; int j;
    if      (i <  49152) { s = w0; d = d0; j = i; }
    else if (i <  65536) { s = w1; d = d1; j = i - 49152; }
    else if (i < 131072) { s = w2; d = d2; j = i - 65536; }
    else                 { s = w3; d = d3; j = i - 131072; }
    float4 v = s[j];
    uint2 o; o.x = bfp(v.x, v.y); o.y = bfp(v.z, v.w);
    d[j] = o;
}

// ---------------- fused attention bias tiles ---------------------------------
__global__ void __launch_bounds__(256) bias_prep(
    const float* __restrict__ rel_bias, const float* __restrict__ mask,
    float* __restrict__ btile)
{
    int h = blockIdx.x >> 6;
    int widx = blockIdx.x & 63;
    float* dst = btile + (size_t)blockIdx.x * (49 * 56);
    const float* mrow = mask + (size_t)widx * 2401;
    for (int e = threadIdx.x; e < 49 * 56; e += 256) {
        int row = e / 56, col = e - row * 56;
        float v = -1e30f;
        if (col < 49) {
            int qi = row / 7, qj = row - qi * 7;
            int ki = col / 7, kj = col - ki * 7;
            int ridx = (qi - ki + 6) * 13 + (qj - kj + 6);
            v = rel_bias[ridx * 8 + h] + mrow[row * 49 + col];
        }
        dst[e] = v;
    }
}

// ---------------- LayerNorm (warp/row; bf16 output) --------------------------
__global__ void __launch_bounds__(256) ln_kernel(
    const float* __restrict__ in, __nv_bfloat16* __restrict__ out,
    const float* __restrict__ gamma, const float* __restrict__ beta,
    int shifted)
{
    int warp = threadIdx.x >> 5, lane = threadIdx.x & 31;
    int t = blockIdx.x * 8 + warp;
    int in_row, out_row;
    if (shifted) {
        int b = t / 3136; int rem = t - b * 3136;
        int i = rem / 56; int j = rem - i * 56;
        int si = i + 3; if (si >= 56) si -= 56;
        int sj = j + 3; if (sj >= 56) sj -= 56;
        in_row = b * 3136 + si * 56 + sj;
        int wb = b * 64 + (i / 7) * 8 + (j / 7);
        int n  = (i % 7) * 7 + (j % 7);
        out_row = wb * 49 + n;
    } else {
        in_row = out_row = t;
    }
    const float4* ip = (const float4*)(in + (size_t)in_row * 256);
    float4 a = ip[lane], b4 = ip[lane + 32];
    float s  = a.x + a.y + a.z + a.w + b4.x + b4.y + b4.z + b4.w;
    float sq = a.x*a.x + a.y*a.y + a.z*a.z + a.w*a.w
             + b4.x*b4.x + b4.y*b4.y + b4.z*b4.z + b4.w*b4.w;
    #pragma unroll
    for (int o = 16; o; o >>= 1) {
        s  += __shfl_xor_sync(0xffffffffu, s,  o);
        sq += __shfl_xor_sync(0xffffffffu, sq, o);
    }
    float mu   = s * (1.0f / 256.0f);
    float var  = sq * (1.0f / 256.0f) - mu * mu;
    float rstd = rsqrtf(var + 1e-5f);
    float4 g0 = ((const float4*)gamma)[lane], g1 = ((const float4*)gamma)[lane + 32];
    float4 e0 = ((const float4*)beta)[lane],  e1 = ((const float4*)beta)[lane + 32];
    uint2* op = (uint2*)(out + (size_t)out_row * 256);
    uint2 w0, w1;
    w0.x = bfp((a.x - mu) * rstd * g0.x + e0.x, (a.y - mu) * rstd * g0.y + e0.y);
    w0.y = bfp((a.z - mu) * rstd * g0.z + e0.z, (a.w - mu) * rstd * g0.w + e0.w);
    w1.x = bfp((b4.x - mu) * rstd * g1.x + e1.x, (b4.y - mu) * rstd * g1.y + e1.y);
    w1.y = bfp((b4.z - mu) * rstd * g1.z + e1.z, (b4.w - mu) * rstd * g1.w + e1.w);
    op[lane] = w0; op[lane + 32] = w1;
}

// ---------------- Tensor-core windowed attention (tf32; bf16 output) ---------
__global__ void __launch_bounds__(128, 6) attn_mma(const float* __restrict__ btile)
{
    int wb = blockIdx.x >> 3;
    int h  = blockIdx.x & 7;
    __shared__ float smem[6144];    // 24KB
    float* qs = smem;               // [64*32]
    float* ks = smem + 2048;        // [56*32]
    float* vt = smem + 4096;        // [32*64]
    float* sc = smem;               // [64*64] overlays qs+ks

    const int t = threadIdx.x;
    const int l = t & 31, w = t >> 5;
    const int ra = l >> 2, ca = l & 3;
    const int mbase = w * 16;
    size_t base = (size_t)blockIdx.x * (49 * 32);
    const float* bt = btile + (size_t)(h * 64 + (wb & 63)) * (49 * 56);

    for (int idx = t; idx < 392; idx += 128) {
        int n = idx >> 3, d4 = (idx & 7) << 2;
        uint32_t wi = (uint32_t)(n << 5) + (d4 ^ ((n & 7) << 2));
        *(float4*)(qs + wi) = *(const float4*)(g_q + base + (n << 5) + d4);
        *(float4*)(ks + wi) = *(const float4*)(g_k + base + (n << 5) + d4);
        float4 vv = *(const float4*)(g_v + base + (n << 5) + d4);
        vt[((d4 + 0) << 6) + (n ^ (((d4 + 0) & 7) << 2))] = vv.x;
        vt[((d4 + 1) << 6) + (n ^ (((d4 + 1) & 7) << 2))] = vv.y;
        vt[((d4 + 2) << 6) + (n ^ (((d4 + 2) & 7) << 2))] = vv.z;
        vt[((d4 + 3) << 6) + (n ^ (((d4 + 3) & 7) << 2))] = vv.w;
    }
    for (int idx = t; idx < 56; idx += 128) {
        int row = 49 + (idx >> 3), d4 = (idx & 7) << 2;
        *(float4*)(ks + (row << 5) + (d4 ^ ((row & 7) << 2))) =
            make_float4(0.f, 0.f, 0.f, 0.f);
    }
    for (int idx = t; idx < 224; idx += 128) {
        int d = idx / 7, m2 = 49 + idx - d * 7;
        vt[(d << 6) + (m2 ^ ((d & 7) << 2))] = 0.f;
    }
    __syncthreads();

    const int r0 = mbase + ra, r1 = r0 + 8;
    const int x0 = (r0 & 7) << 2, x1 = (r1 & 7) << 2;

    float acc[7][4];
    #pragma unroll
    for (int nt = 0; nt < 7; nt++)
        #pragma unroll
        for (int j = 0; j < 4; j++) acc[nt][j] = 0.f;

    #pragma unroll
    for (int k0 = 0; k0 < 32; k0 += 8) {
        uint32_t af[4];
        af[0] = f2u(qs[(r0 << 5) + ((k0 + ca)     ^ x0)]);
        af[1] = f2u(qs[(r1 << 5) + ((k0 + ca)     ^ x1)]);
        af[2] = f2u(qs[(r0 << 5) + ((k0 + ca + 4) ^ x0)]);
        af[3] = f2u(qs[(r1 << 5) + ((k0 + ca + 4) ^ x1)]);
        #pragma unroll
        for (int nt = 0; nt < 7; nt++) {
            int n = nt * 8 + ra;
            int xn = (n & 7) << 2;
            uint32_t bf[2];
            bf[0] = f2u(ks[(n << 5) + ((k0 + ca)     ^ xn)]);
            bf[1] = f2u(ks[(n << 5) + ((k0 + ca + 4) ^ xn)]);
            mma8(acc[nt], af, bf);
        }
    }

    #pragma unroll
    for (int nt = 0; nt < 7; nt++) {
        int cb = nt * 8 + 2 * ca;
        if (r0 < 49) {
            float2 b0 = *(const float2*)(bt + r0 * 56 + cb);
            acc[nt][0] += b0.x; acc[nt][1] += b0.y;
        } else { acc[nt][0] = -1e30f; acc[nt][1] = -1e30f; }
        if (r1 < 49) {
            float2 b1 = *(const float2*)(bt + r1 * 56 + cb);
            acc[nt][2] += b1.x; acc[nt][3] += b1.y;
        } else { acc[nt][2] = -1e30f; acc[nt][3] = -1e30f; }
    }

    float m0 = -1e30f, m1 = -1e30f;
    #pragma unroll
    for (int nt = 0; nt < 7; nt++) {
        m0 = fmaxf(m0, fmaxf(acc[nt][0], acc[nt][1]));
        m1 = fmaxf(m1, fmaxf(acc[nt][2], acc[nt][3]));
    }
    m0 = fmaxf(m0, __shfl_xor_sync(0xffffffffu, m0, 1));
    m0 = fmaxf(m0, __shfl_xor_sync(0xffffffffu, m0, 2));
    m1 = fmaxf(m1, __shfl_xor_sync(0xffffffffu, m1, 1));
    m1 = fmaxf(m1, __shfl_xor_sync(0xffffffffu, m1, 2));
    float s0 = 0.f, s1 = 0.f;
    #pragma unroll
    for (int nt = 0; nt < 7; nt++) {
        acc[nt][0] = __expf(acc[nt][0] - m0); s0 += acc[nt][0];
        acc[nt][1] = __expf(acc[nt][1] - m0); s0 += acc[nt][1];
        acc[nt][2] = __expf(acc[nt][2] - m1); s1 += acc[nt][2];
        acc[nt][3] = __expf(acc[nt][3] - m1); s1 += acc[nt][3];
    }
    s0 += __shfl_xor_sync(0xffffffffu, s0, 1);
    s0 += __shfl_xor_sync(0xffffffffu, s0, 2);
    s1 += __shfl_xor_sync(0xffffffffu, s1, 1);
    s1 += __shfl_xor_sync(0xffffffffu, s1, 2);
    float i0 = 1.0f / s0, i1 = 1.0f / s1;

    __syncthreads();

    #pragma unroll
    for (int nt = 0; nt < 7; nt++) {
        int cb = nt * 8 + 2 * ca;
        *(float2*)(sc + (r0 << 6) + (cb ^ x0)) =
            make_float2(acc[nt][0] * i0, acc[nt][1] * i0);
        *(float2*)(sc + (r1 << 6) + (cb ^ x1)) =
            make_float2(acc[nt][2] * i1, acc[nt][3] * i1);
    }
    __syncthreads();

    float o[4][4];
    #pragma unroll
    for (int nt = 0; nt < 4; nt++)
        #pragma unroll
        for (int j = 0; j < 4; j++) o[nt][j] = 0.f;

    #pragma unroll
    for (int k0 = 0; k0 < 56; k0 += 8) {
        uint32_t af[4];
        af[0] = f2u(sc[(r0 << 6) + ((k0 + ca)     ^ x0)]);
        af[1] = f2u(sc[(r1 << 6) + ((k0 + ca)     ^ x1)]);
        af[2] = f2u(sc[(r0 << 6) + ((k0 + ca + 4) ^ x0)]);
        af[3] = f2u(sc[(r1 << 6) + ((k0 + ca + 4) ^ x1)]);
        #pragma unroll
        for (int nt = 0; nt < 4; nt++) {
            int n = nt * 8 + ra;
            int xn = (n & 7) << 2;
            uint32_t bf[2];
            bf[0] = f2u(vt[(n << 6) + ((k0 + ca)     ^ xn)]);
            bf[1] = f2u(vt[(n << 6) + ((k0 + ca + 4) ^ xn)]);
            mma8(o[nt], af, bf);
        }
    }

    // store O as bf16 (feeds proj GEMM)
    #pragma unroll
    for (int half = 0; half < 2; half++) {
        int row = mbase + ra + half * 8;
        if (row < 49) {
            __nv_bfloat16* dst = g_o_bf + ((size_t)(wb * 49 + row)) * 256 + h * 32;
            #pragma unroll
            for (int nt = 0; nt < 4; nt++) {
                int col = nt * 8 + 2 * ca;
                *(uint32_t*)(dst + col) =
                    bfp(o[nt][half * 2 + 0], o[nt][half * 2 + 1]);
            }
        }
    }
}

// ---------------- bf16 mma.sync GEMM NT, 128x128 tile, K-chunk 64, 3-stage ---
// D[M,N] = A[M,K] @ B[N,K]^T, bf16 in, fp32 accum.
// Same 128-B smem rows / swizzle / fragment word-indices as the tf32 version;
// each word now holds a bf16 k-pair so one iteration covers K=64.
// MODE 0: QKV  (bias; scatter q*SCALE / k / v f32 (tf32-rounded) for attention)
// MODE 1: proj (bias; window-reverse + un-roll; + residual) -> f32
// MODE 2: fc1  (bias; exact GELU) -> bf16
// MODE 3: fc2  (bias; + residual) -> f32
constexpr int GEMM_SMEM = 98304;   // 3 stages x (16K A + 16K B)

template <int MODE>
__global__ void __launch_bounds__(256, 2) mma_gemm(
    const __nv_bfloat16* __restrict__ A, const __nv_bfloat16* __restrict__ B,
    const float* __restrict__ bias, const float* __restrict__ res,
    float* __restrict__ O0, float* __restrict__ O1, float* __restrict__ O2,
    __nv_bfloat16* __restrict__ Ob, int K, int ldo)
{
    extern __shared__ float dsm[];
    const int t = threadIdx.x;
    const int rowBase = blockIdx.y * 128;
    const int colBase = blockIdx.x * 128;
    const uint32_t sbase = smem_u32(dsm);

    // producer: thread t loads row (t>>1), 64B half (t&1) as 4x16B
    const int pr = t >> 1, ph = t & 1;
    const __nv_bfloat16* Ap = A + (size_t)(rowBase + pr) * K + ph * 32;
    const __nv_bfloat16* Bp = B + (size_t)(colBase + pr) * K + ph * 32;
    uint32_t poff[4];
    #pragma unroll
    for (int s = 0; s < 4; s++)
        poff[s] = swz((uint32_t)pr * 128u + (uint32_t)(ph * 4 + s) * 16u);

    const int T = K >> 6;   // K-chunks of 64
    #pragma unroll
    for (int p = 0; p < 2; p++) {
        uint32_t sA = sbase + (uint32_t)p * 32768u, sB = sA + 16384u;
        #pragma unroll
        for (int s = 0; s < 4; s++) {
            cp16(sA + poff[s], Ap + p * 64 + s * 8);
            cp16(sB + poff[s], Bp + p * 64 + s * 8);
        }
        cp_commit();
    }

    const int l = t & 31, w = t >> 5;
    const int wr = w >> 2, wc = w & 3;
    const int ra = l >> 2, ca = l & 3;

    float c[4][4][4];
    #pragma unroll
    for (int mt = 0; mt < 4; mt++)
        #pragma unroll
        for (int nt = 0; nt < 4; nt++)
            #pragma unroll
            for (int j = 0; j < 4; j++) c[mt][nt][j] = 0.f;

    int stage = 0;
    for (int i = 0; i < T; i++) {
        cp_wait<1>();
        __syncthreads();
        if (i + 2 < T) {
            int ws = stage + 2; if (ws >= 3) ws -= 3;
            uint32_t sA = sbase + (uint32_t)ws * 32768u, sB = sA + 16384u;
            #pragma unroll
            for (int s = 0; s < 4; s++) {
                cp16(sA + poff[s], Ap + (i + 2) * 64 + s * 8);
                cp16(sB + poff[s], Bp + (i + 2) * 64 + s * 8);
            }
        }
        cp_commit();

        const uint32_t* As = (const uint32_t*)dsm + stage * 8192;
        const uint32_t* Bs = As + 4096;
        #pragma unroll
        for (int kk = 0; kk < 4; kk++) {
            const int k0 = kk * 8;    // word index: 8 words = 16 bf16 per mma
            uint32_t af[4][4], bf[4][2];
            #pragma unroll
            for (int mt = 0; mt < 4; mt++) {
                int m = wr * 64 + mt * 16 + ra;
                int x = (m & 7) << 2;
                const uint32_t* P  = As + m * 32;
                const uint32_t* P2 = As + (m + 8) * 32;
                af[mt][0] = P [(k0 + ca)     ^ x];
                af[mt][1] = P2[(k0 + ca)     ^ x];
                af[mt][2] = P [(k0 + ca + 4) ^ x];
                af[mt][3] = P2[(k0 + ca + 4) ^ x];
            }
            #pragma unroll
            for (int nt = 0; nt < 4; nt++) {
                int n = wc * 32 + nt * 8 + ra;
                int x = (n & 7) << 2;
                const uint32_t* P = Bs + n * 32;
                bf[nt][0] = P[(k0 + ca)     ^ x];
                bf[nt][1] = P[(k0 + ca + 4) ^ x];
            }
            #pragma unroll
            for (int mt = 0; mt < 4; mt++)
                #pragma unroll
                for (int nt = 0; nt < 4; nt++)
                    mma16(c[mt][nt], af[mt], bf[nt]);
        }
        stage = (stage == 2) ? 0 : stage + 1;
    }

    // ---------------- epilogue ----------------
    #pragma unroll
    for (int mt = 0; mt < 4; mt++) {
        #pragma unroll
        for (int rr = 0; rr < 2; rr++) {
            const int gm = rowBase + wr * 64 + mt * 16 + ra + rr * 8;
            int wb = 0, n = 0; size_t orow = 0;
            if (MODE == 0) { wb = gm / 49; n = gm - wb * 49; }
            if (MODE == 1) {
                wb = gm / 49; n = gm - wb * 49;
                int b = wb >> 6; int widx = wb & 63;
                int ii = (widx >> 3) * 7 + n / 7;
                int jj = (widx & 7) * 7 + n % 7;
                int oi = ii + 3; if (oi >= 56) oi -= 56;
                int oj = jj + 3; if (oj >= 56) oj -= 56;
                orow = ((size_t)b * 3136 + oi * 56 + oj) * 256;
            }
            if (MODE == 2 || MODE == 3) orow = (size_t)gm * ldo;

            #pragma unroll
            for (int nt = 0; nt < 4; nt++) {
                const int gc = colBase + wc * 32 + nt * 8 + 2 * ca;
                float2 bb = *(const float2*)(bias + gc);
                float v0 = c[mt][nt][rr * 2 + 0] + bb.x;
                float v1 = c[mt][nt][rr * 2 + 1] + bb.y;

                if (MODE == 0) {
                    int part = gc >> 8;
                    int hh = (gc >> 5) & 7;
                    int dd = gc & 31;
                    float* Op = (part == 0) ? O0 : ((part == 1) ? O1 : O2);
                    if (part == 0) { v0 *= SCALE; v1 *= SCALE; }
                    *(float2*)(Op + (((size_t)wb * 8 + hh) * 49 + n) * 32 + dd)
                        = make_float2(to_tf32(v0), to_tf32(v1));
                } else if (MODE == 1) {
                    float2 rr2 = *(const float2*)(res + orow + gc);
                    *(float2*)(O0 + orow + gc) = make_float2(rr2.x + v0, rr2.y + v1);
                } else if (MODE == 2) {
                    v0 = 0.5f * v0 * (1.0f + erff(v0 * 0.70710678118654752f));
                    v1 = 0.5f * v1 * (1.0f + erff(v1 * 0.70710678118654752f));
                    *(uint32_t*)(Ob + orow + gc) = bfp(v0, v1);
                } else {
                    float2 rr2 = *(const float2*)(res + orow + gc);
                    *(float2*)(O0 + orow + gc) = make_float2(rr2.x + v0, rr2.y + v1);
                }
            }
        }
    }
}

// ----------------------------------------------------------------------------
extern "C" void kernel_launch(void* const* d_in, const int* in_sizes, int n_in,
                              void* d_out, int out_size)
{
    const float* x      = (const float*)d_in[0];
    const float* mask   = (const float*)d_in[1];
    const float* n1g    = (const float*)d_in[2];
    const float* n1b    = (const float*)d_in[3];
    const float* qkv_w  = (const float*)d_in[4];
    const float* qkv_b  = (const float*)d_in[5];
    const float* relb   = (const float*)d_in[6];
    const float* proj_w = (const float*)d_in[7];
    const float* proj_b = (const float*)d_in[8];
    const float* n2g    = (const float*)d_in[9];
    const float* n2b    = (const float*)d_in[10];
    const float* fc1_w  = (const float*)d_in[11];
    const float* fc1_b  = (const float*)d_in[12];
    const float* fc2_w  = (const float*)d_in[13];
    const float* fc2_b  = (const float*)d_in[14];
    float* out = (float*)d_out;

    float *p_q, *p_k, *p_v, *p_x2, *p_btile;
    __nv_bfloat16 *p_hw, *p_o, *p_h2n, *p_mlp;
    __nv_bfloat16 *p_wqkv, *p_wprj, *p_wfc1, *p_wfc2;
    cudaGetSymbolAddress((void**)&p_q,     g_q);
    cudaGetSymbolAddress((void**)&p_k,     g_k);
    cudaGetSymbolAddress((void**)&p_v,     g_v);
    cudaGetSymbolAddress((void**)&p_x2,    g_x2);
    cudaGetSymbolAddress((void**)&p_btile, g_btile);
    cudaGetSymbolAddress((void**)&p_hw,    g_hw_bf);
    cudaGetSymbolAddress((void**)&p_o,     g_o_bf);
    cudaGetSymbolAddress((void**)&p_h2n,   g_h2n_bf);
    cudaGetSymbolAddress((void**)&p_mlp,   g_mlp_bf);
    cudaGetSymbolAddress((void**)&p_wqkv,  g_wqkv_bf);
    cudaGetSymbolAddress((void**)&p_wprj,  g_wprj_bf);
    cudaGetSymbolAddress((void**)&p_wfc1,  g_wfc1_bf);
    cudaGetSymbolAddress((void**)&p_wfc2,  g_wfc2_bf);

    cudaFuncSetAttribute(mma_gemm<0>, cudaFuncAttributeMaxDynamicSharedMemorySize, GEMM_SMEM);
    cudaFuncSetAttribute(mma_gemm<1>, cudaFuncAttributeMaxDynamicSharedMemorySize, GEMM_SMEM);
    cudaFuncSetAttribute(mma_gemm<2>, cudaFuncAttributeMaxDynamicSharedMemorySize, GEMM_SMEM);
    cudaFuncSetAttribute(mma_gemm<3>, cudaFuncAttributeMaxDynamicSharedMemorySize, GEMM_SMEM);

    wcvt_all<<<768, 256>>>((const float4*)qkv_w, (const float4*)proj_w,
                           (const float4*)fc1_w, (const float4*)fc2_w,
                           (uint2*)p_wqkv, (uint2*)p_wprj,
                           (uint2*)p_wfc1, (uint2*)p_wfc2);
    bias_prep<<<512, 256>>>(relb, mask, p_btile);
    // 1. LN1 + shift + window partition -> bf16
    ln_kernel<<<TOKENS / 8, 256>>>(x, p_hw, n1g, n1b, 1);
    // 2. QKV (bf16 mma) -> q(scaled)/k/v f32 in (wb,h,n,d)
    mma_gemm<0><<<dim3(6, 392), 256, GEMM_SMEM>>>(p_hw, p_wqkv, qkv_b, nullptr,
                                                  p_q, p_k, p_v, nullptr, 256, 0);
    // 3. Windowed MSA (tf32 tensor-core) -> bf16
    attn_mma<<<8192, 128>>>(p_btile);
    // 4. proj (bf16 mma) + window-reverse + un-roll + residual(x) -> f32
    mma_gemm<1><<<dim3(2, 392), 256, GEMM_SMEM>>>(p_o, p_wprj, proj_b, x,
                                                  p_x2, nullptr, nullptr, nullptr, 256, 256);
    // 5. LN2 -> bf16
    ln_kernel<<<TOKENS / 8, 256>>>(p_x2, p_h2n, n2g, n2b, 0);
    // 6. fc1 (bf16 mma) + GELU -> bf16
    mma_gemm<2><<<dim3(8, 392), 256, GEMM_SMEM>>>(p_h2n, p_wfc1, fc1_b, nullptr,
                                                  nullptr, nullptr, nullptr, p_mlp, 256, 1024);
    // 7. fc2 (bf16 mma) + residual(x2) -> out
    mma_gemm<3><<<dim3(2, 392), 256, GEMM_SMEM>>>(p_mlp, p_wfc2, fc2_b, p_x2,
                                                  out, nullptr, nullptr, nullptr, 1024, 256);
}

// round 11
// speedup vs baseline: 5.3967x; 1.0325x over previous
#include <cuda_runtime.h>
#include <cuda_bf16.h>
#include <cstdint>

#define DEVFN __device__ __forceinline__

constexpr int TOKENS = 16 * 56 * 56;   // 50176
constexpr float SCALE = 0.17677669529663687f;   // 32^-0.5

// Scratch (static device arrays: allocation-free per harness rules)
__device__ float g_q   [TOKENS * 256];
__device__ float g_k   [TOKENS * 256];
__device__ float g_v   [TOKENS * 256];
__device__ float g_x2  [TOKENS * 256];
__device__ float g_btile[512 * 49 * 56];            // fused rel_bias+mask
__device__ __nv_bfloat16 g_hw_bf [TOKENS * 256];    // LN1 out (windowed)
__device__ __nv_bfloat16 g_o_bf  [TOKENS * 256];    // attention out
__device__ __nv_bfloat16 g_h2n_bf[TOKENS * 256];    // LN2 out
__device__ __nv_bfloat16 g_mlp_bf[TOKENS * 1024];   // fc1+gelu out
__device__ __nv_bfloat16 g_wqkv_bf[768 * 256];
__device__ __nv_bfloat16 g_wprj_bf[256 * 256];
__device__ __nv_bfloat16 g_wfc1_bf[1024 * 256];
__device__ __nv_bfloat16 g_wfc2_bf[256 * 1024];

// ------------------------------ PTX helpers ---------------------------------
DEVFN uint32_t smem_u32(const void* p) {
    uint32_t a;
    asm("{ .reg .u64 t; cvta.to.shared.u64 t, %1; cvt.u32.u64 %0, t; }"
        : "=r"(a) : "l"(p));
    return a;
}
DEVFN uint32_t swz(uint32_t o) { return o ^ ((o >> 3) & 0x70u); }
DEVFN void cp16(uint32_t dst, const void* src) {
    asm volatile("cp.async.cg.shared.global [%0], [%1], 16;" :: "r"(dst), "l"(src));
}
DEVFN void cp_commit() { asm volatile("cp.async.commit_group;" ::: "memory"); }
template <int N> DEVFN void cp_wait() {
    asm volatile("cp.async.wait_group %0;" :: "n"(N) : "memory");
}
DEVFN float to_tf32(float x) {
    float r;
    asm("cvt.rna.tf32.f32 %0, %1;" : "=f"(r) : "f"(x));
    return r;
}
DEVFN uint32_t bfp(float a, float b) {   // pack 2 floats -> bf16x2 (RNE)
    __nv_bfloat162 t = __floats2bfloat162_rn(a, b);
    return *(uint32_t*)&t;
}
// tf32 mma (attention)
DEVFN void mma8(float c[4], const uint32_t a[4], const uint32_t b[2]) {
    asm volatile(
        "mma.sync.aligned.m16n8k8.row.col.f32.tf32.tf32.f32 "
        "{%0,%1,%2,%3}, {%4,%5,%6,%7}, {%8,%9}, {%0,%1,%2,%3};"
        : "+f"(c[0]), "+f"(c[1]), "+f"(c[2]), "+f"(c[3])
        : "r"(a[0]), "r"(a[1]), "r"(a[2]), "r"(a[3]), "r"(b[0]), "r"(b[1]));
}
// bf16 mma (GEMMs): K=16 per instruction
DEVFN void mma16(float c[4], const uint32_t a[4], const uint32_t b[2]) {
    asm volatile(
        "mma.sync.aligned.m16n8k16.row.col.f32.bf16.bf16.f32 "
        "{%0,%1,%2,%3}, {%4,%5,%6,%7}, {%8,%9}, {%0,%1,%2,%3};"
        : "+f"(c[0]), "+f"(c[1]), "+f"(c[2]), "+f"(c[3])
        : "r"(a[0]), "r"(a[1]), "r"(a[2]), "r"(a[3]), "r"(b[0]), "r"(b[1]));
}
DEVFN void ldsm4(uint32_t r[4], uint32_t addr) {
    asm volatile("ldmatrix.sync.aligned.m8n8.x4.shared.b16 {%0,%1,%2,%3}, [%4];"
        : "=r"(r[0]), "=r"(r[1]), "=r"(r[2]), "=r"(r[3]) : "r"(addr));
}
DEVFN void ldsm2(uint32_t r[2], uint32_t addr) {
    asm volatile("ldmatrix.sync.aligned.m8n8.x2.shared.b16 {%0,%1}, [%2];"
        : "=r"(r[0]), "=r"(r[1]) : "r"(addr));
}
DEVFN uint32_t f2u(float x) { return __float_as_uint(x); }

// ---------------- all-weights f32 -> bf16 (RNE), single launch ---------------
__global__ void __launch_bounds__(256) wcvt_all(
    const float4* __restrict__ w0, const float4* __restrict__ w1,
    const float4* __restrict__ w2, const float4* __restrict__ w3,
    uint2* __restrict__ d0, uint2* __restrict__ d1,
    uint2* __restrict__ d2, uint2* __restrict__ d3)
{
    int i = blockIdx.x * 256 + threadIdx.x;
    const float4* s; uint2* d; int j;
    if      (i <  49152) { s = w0; d = d0; j = i; }
    else if (i <  65536) { s = w1; d = d1; j = i - 49152; }
    else if (i < 131072) { s = w2; d = d2; j = i - 65536; }
    else                 { s = w3; d = d3; j = i - 131072; }
    float4 v = s[j];
    uint2 o; o.x = bfp(v.x, v.y); o.y = bfp(v.z, v.w);
    d[j] = o;
}

// ---------------- fused attention bias tiles ---------------------------------
__global__ void __launch_bounds__(256) bias_prep(
    const float* __restrict__ rel_bias, const float* __restrict__ mask,
    float* __restrict__ btile)
{
    int h = blockIdx.x >> 6;
    int widx = blockIdx.x & 63;
    float* dst = btile + (size_t)blockIdx.x * (49 * 56);
    const float* mrow = mask + (size_t)widx * 2401;
    for (int e = threadIdx.x; e < 49 * 56; e += 256) {
        int row = e / 56, col = e - row * 56;
        float v = -1e30f;
        if (col < 49) {
            int qi = row / 7, qj = row - qi * 7;
            int ki = col / 7, kj = col - ki * 7;
            int ridx = (qi - ki + 6) * 13 + (qj - kj + 6);
            v = rel_bias[ridx * 8 + h] + mrow[row * 49 + col];
        }
        dst[e] = v;
    }
}

// ---------------- LayerNorm (warp/row; bf16 output) --------------------------
__global__ void __launch_bounds__(256) ln_kernel(
    const float* __restrict__ in, __nv_bfloat16* __restrict__ out,
    const float* __restrict__ gamma, const float* __restrict__ beta,
    int shifted)
{
    int warp = threadIdx.x >> 5, lane = threadIdx.x & 31;
    int t = blockIdx.x * 8 + warp;
    int in_row, out_row;
    if (shifted) {
        int b = t / 3136; int rem = t - b * 3136;
        int i = rem / 56; int j = rem - i * 56;
        int si = i + 3; if (si >= 56) si -= 56;
        int sj = j + 3; if (sj >= 56) sj -= 56;
        in_row = b * 3136 + si * 56 + sj;
        int wb = b * 64 + (i / 7) * 8 + (j / 7);
        int n  = (i % 7) * 7 + (j % 7);
        out_row = wb * 49 + n;
    } else {
        in_row = out_row = t;
    }
    const float4* ip = (const float4*)(in + (size_t)in_row * 256);
    float4 a = ip[lane], b4 = ip[lane + 32];
    float s  = a.x + a.y + a.z + a.w + b4.x + b4.y + b4.z + b4.w;
    float sq = a.x*a.x + a.y*a.y + a.z*a.z + a.w*a.w
             + b4.x*b4.x + b4.y*b4.y + b4.z*b4.z + b4.w*b4.w;
    #pragma unroll
    for (int o = 16; o; o >>= 1) {
        s  += __shfl_xor_sync(0xffffffffu, s,  o);
        sq += __shfl_xor_sync(0xffffffffu, sq, o);
    }
    float mu   = s * (1.0f / 256.0f);
    float var  = sq * (1.0f / 256.0f) - mu * mu;
    float rstd = rsqrtf(var + 1e-5f);
    float4 g0 = ((const float4*)gamma)[lane], g1 = ((const float4*)gamma)[lane + 32];
    float4 e0 = ((const float4*)beta)[lane],  e1 = ((const float4*)beta)[lane + 32];
    uint2* op = (uint2*)(out + (size_t)out_row * 256);
    uint2 w0, w1;
    w0.x = bfp((a.x - mu) * rstd * g0.x + e0.x, (a.y - mu) * rstd * g0.y + e0.y);
    w0.y = bfp((a.z - mu) * rstd * g0.z + e0.z, (a.w - mu) * rstd * g0.w + e0.w);
    w1.x = bfp((b4.x - mu) * rstd * g1.x + e1.x, (b4.y - mu) * rstd * g1.y + e1.y);
    w1.y = bfp((b4.z - mu) * rstd * g1.z + e1.z, (b4.w - mu) * rstd * g1.w + e1.w);
    op[lane] = w0; op[lane + 32] = w1;
}

// ---------------- Tensor-core windowed attention (tf32; bf16 output) ---------
__global__ void __launch_bounds__(128, 6) attn_mma(const float* __restrict__ btile)
{
    int wb = blockIdx.x >> 3;
    int h  = blockIdx.x & 7;
    __shared__ float smem[6144];    // 24KB
    float* qs = smem;               // [64*32]
    float* ks = smem + 2048;        // [56*32]
    float* vt = smem + 4096;        // [32*64]
    float* sc = smem;               // [64*64] overlays qs+ks

    const int t = threadIdx.x;
    const int l = t & 31, w = t >> 5;
    const int ra = l >> 2, ca = l & 3;
    const int mbase = w * 16;
    size_t base = (size_t)blockIdx.x * (49 * 32);
    const float* bt = btile + (size_t)(h * 64 + (wb & 63)) * (49 * 56);

    for (int idx = t; idx < 392; idx += 128) {
        int n = idx >> 3, d4 = (idx & 7) << 2;
        uint32_t wi = (uint32_t)(n << 5) + (d4 ^ ((n & 7) << 2));
        *(float4*)(qs + wi) = *(const float4*)(g_q + base + (n << 5) + d4);
        *(float4*)(ks + wi) = *(const float4*)(g_k + base + (n << 5) + d4);
        float4 vv = *(const float4*)(g_v + base + (n << 5) + d4);
        vt[((d4 + 0) << 6) + (n ^ (((d4 + 0) & 7) << 2))] = vv.x;
        vt[((d4 + 1) << 6) + (n ^ (((d4 + 1) & 7) << 2))] = vv.y;
        vt[((d4 + 2) << 6) + (n ^ (((d4 + 2) & 7) << 2))] = vv.z;
        vt[((d4 + 3) << 6) + (n ^ (((d4 + 3) & 7) << 2))] = vv.w;
    }
    for (int idx = t; idx < 56; idx += 128) {
        int row = 49 + (idx >> 3), d4 = (idx & 7) << 2;
        *(float4*)(ks + (row << 5) + (d4 ^ ((row & 7) << 2))) =
            make_float4(0.f, 0.f, 0.f, 0.f);
    }
    for (int idx = t; idx < 224; idx += 128) {
        int d = idx / 7, m2 = 49 + idx - d * 7;
        vt[(d << 6) + (m2 ^ ((d & 7) << 2))] = 0.f;
    }
    __syncthreads();

    const int r0 = mbase + ra, r1 = r0 + 8;
    const int x0 = (r0 & 7) << 2, x1 = (r1 & 7) << 2;

    float acc[7][4];
    #pragma unroll
    for (int nt = 0; nt < 7; nt++)
        #pragma unroll
        for (int j = 0; j < 4; j++) acc[nt][j] = 0.f;

    #pragma unroll
    for (int k0 = 0; k0 < 32; k0 += 8) {
        uint32_t af[4];
        af[0] = f2u(qs[(r0 << 5) + ((k0 + ca)     ^ x0)]);
        af[1] = f2u(qs[(r1 << 5) + ((k0 + ca)     ^ x1)]);
        af[2] = f2u(qs[(r0 << 5) + ((k0 + ca + 4) ^ x0)]);
        af[3] = f2u(qs[(r1 << 5) + ((k0 + ca + 4) ^ x1)]);
        #pragma unroll
        for (int nt = 0; nt < 7; nt++) {
            int n = nt * 8 + ra;
            int xn = (n & 7) << 2;
            uint32_t bf[2];
            bf[0] = f2u(ks[(n << 5) + ((k0 + ca)     ^ xn)]);
            bf[1] = f2u(ks[(n << 5) + ((k0 + ca + 4) ^ xn)]);
            mma8(acc[nt], af, bf);
        }
    }

    #pragma unroll
    for (int nt = 0; nt < 7; nt++) {
        int cb = nt * 8 + 2 * ca;
        if (r0 < 49) {
            float2 b0 = *(const float2*)(bt + r0 * 56 + cb);
            acc[nt][0] += b0.x; acc[nt][1] += b0.y;
        } else { acc[nt][0] = -1e30f; acc[nt][1] = -1e30f; }
        if (r1 < 49) {
            float2 b1 = *(const float2*)(bt + r1 * 56 + cb);
            acc[nt][2] += b1.x; acc[nt][3] += b1.y;
        } else { acc[nt][2] = -1e30f; acc[nt][3] = -1e30f; }
    }

    float m0 = -1e30f, m1 = -1e30f;
    #pragma unroll
    for (int nt = 0; nt < 7; nt++) {
        m0 = fmaxf(m0, fmaxf(acc[nt][0], acc[nt][1]));
        m1 = fmaxf(m1, fmaxf(acc[nt][2], acc[nt][3]));
    }
    m0 = fmaxf(m0, __shfl_xor_sync(0xffffffffu, m0, 1));
    m0 = fmaxf(m0, __shfl_xor_sync(0xffffffffu, m0, 2));
    m1 = fmaxf(m1, __shfl_xor_sync(0xffffffffu, m1, 1));
    m1 = fmaxf(m1, __shfl_xor_sync(0xffffffffu, m1, 2));
    float s0 = 0.f, s1 = 0.f;
    #pragma unroll
    for (int nt = 0; nt < 7; nt++) {
        acc[nt][0] = __expf(acc[nt][0] - m0); s0 += acc[nt][0];
        acc[nt][1] = __expf(acc[nt][1] - m0); s0 += acc[nt][1];
        acc[nt][2] = __expf(acc[nt][2] - m1); s1 += acc[nt][2];
        acc[nt][3] = __expf(acc[nt][3] - m1); s1 += acc[nt][3];
    }
    s0 += __shfl_xor_sync(0xffffffffu, s0, 1);
    s0 += __shfl_xor_sync(0xffffffffu, s0, 2);
    s1 += __shfl_xor_sync(0xffffffffu, s1, 1);
    s1 += __shfl_xor_sync(0xffffffffu, s1, 2);
    float i0 = 1.0f / s0, i1 = 1.0f / s1;

    __syncthreads();

    #pragma unroll
    for (int nt = 0; nt < 7; nt++) {
        int cb = nt * 8 + 2 * ca;
        *(float2*)(sc + (r0 << 6) + (cb ^ x0)) =
            make_float2(acc[nt][0] * i0, acc[nt][1] * i0);
        *(float2*)(sc + (r1 << 6) + (cb ^ x1)) =
            make_float2(acc[nt][2] * i1, acc[nt][3] * i1);
    }
    __syncthreads();

    float o[4][4];
    #pragma unroll
    for (int nt = 0; nt < 4; nt++)
        #pragma unroll
        for (int j = 0; j < 4; j++) o[nt][j] = 0.f;

    #pragma unroll
    for (int k0 = 0; k0 < 56; k0 += 8) {
        uint32_t af[4];
        af[0] = f2u(sc[(r0 << 6) + ((k0 + ca)     ^ x0)]);
        af[1] = f2u(sc[(r1 << 6) + ((k0 + ca)     ^ x1)]);
        af[2] = f2u(sc[(r0 << 6) + ((k0 + ca + 4) ^ x0)]);
        af[3] = f2u(sc[(r1 << 6) + ((k0 + ca + 4) ^ x1)]);
        #pragma unroll
        for (int nt = 0; nt < 4; nt++) {
            int n = nt * 8 + ra;
            int xn = (n & 7) << 2;
            uint32_t bf[2];
            bf[0] = f2u(vt[(n << 6) + ((k0 + ca)     ^ xn)]);
            bf[1] = f2u(vt[(n << 6) + ((k0 + ca + 4) ^ xn)]);
            mma8(o[nt], af, bf);
        }
    }

    // store O as bf16 (feeds proj GEMM)
    #pragma unroll
    for (int half = 0; half < 2; half++) {
        int row = mbase + ra + half * 8;
        if (row < 49) {
            __nv_bfloat16* dst = g_o_bf + ((size_t)(wb * 49 + row)) * 256 + h * 32;
            #pragma unroll
            for (int nt = 0; nt < 4; nt++) {
                int col = nt * 8 + 2 * ca;
                *(uint32_t*)(dst + col) =
                    bfp(o[nt][half * 2 + 0], o[nt][half * 2 + 1]);
            }
        }
    }
}

// ---------------- bf16 mma.sync GEMM NT, 128x128 tile, K-chunk 64, 3-stage ---
// Fragment loads via ldmatrix (x4 for A, x2 for B): 8 LDSM per kk-step vs 24 LDS.
// MODE 0: QKV  (bias; scatter q*SCALE / k / v f32 (tf32-rounded) for attention)
// MODE 1: proj (bias; window-reverse + un-roll; + residual) -> f32
// MODE 2: fc1  (bias; exact GELU) -> bf16
// MODE 3: fc2  (bias; + residual) -> f32
constexpr int GEMM_SMEM = 98304;   // 3 stages x (16K A + 16K B)

template <int MODE>
__global__ void __launch_bounds__(256, 2) mma_gemm(
    const __nv_bfloat16* __restrict__ A, const __nv_bfloat16* __restrict__ B,
    const float* __restrict__ bias, const float* __restrict__ res,
    float* __restrict__ O0, float* __restrict__ O1, float* __restrict__ O2,
    __nv_bfloat16* __restrict__ Ob, int K, int ldo)
{
    extern __shared__ float dsm[];
    const int t = threadIdx.x;
    const int rowBase = blockIdx.y * 128;
    const int colBase = blockIdx.x * 128;
    const uint32_t sbase = smem_u32(dsm);

    // producer: thread t loads row (t>>1), 64B half (t&1) as 4x16B
    const int pr = t >> 1, ph = t & 1;
    const __nv_bfloat16* Ap = A + (size_t)(rowBase + pr) * K + ph * 32;
    const __nv_bfloat16* Bp = B + (size_t)(colBase + pr) * K + ph * 32;
    uint32_t poff[4];
    #pragma unroll
    for (int s = 0; s < 4; s++)
        poff[s] = swz((uint32_t)pr * 128u + (uint32_t)(ph * 4 + s) * 16u);

    const int T = K >> 6;   // K-chunks of 64
    #pragma unroll
    for (int p = 0; p < 2; p++) {
        uint32_t sA = sbase + (uint32_t)p * 32768u, sB = sA + 16384u;
        #pragma unroll
        for (int s = 0; s < 4; s++) {
            cp16(sA + poff[s], Ap + p * 64 + s * 8);
            cp16(sB + poff[s], Bp + p * 64 + s * 8);
        }
        cp_commit();
    }

    const int l = t & 31, w = t >> 5;
    const int wr = w >> 2, wc = w & 3;
    const int ra = l >> 2, ca = l & 3;

    // ldmatrix per-lane address components.
    // A .x4: matrices (g=l>>3): 0: rows m+r @k0 | 1: m+8+r @k0 | 2: m+r @k0+8 | 3: m+8+r @k0+8
    // B .x2: lanes 0-7: rows n0+r @k0; lanes 8-15: rows n0+r @k0+8
    const int r8 = l & 7, g8 = l >> 3;
    const uint32_t xw = (uint32_t)r8 << 2;             // swizzle XOR (word units)
    const uint32_t aKC = (uint32_t)(g8 >> 1) * 4u;     // A: +8 bf16 for matrices 2,3
    const uint32_t bKC = (uint32_t)(g8 & 1) * 4u;      // B: +8 bf16 for matrix 1
    uint32_t aRow[4], bRow[4];
    #pragma unroll
    for (int mt = 0; mt < 4; mt++)
        aRow[mt] = (uint32_t)(wr * 64 + mt * 16 + (g8 & 1) * 8 + r8) * 128u;
    #pragma unroll
    for (int nt = 0; nt < 4; nt++)
        bRow[nt] = (uint32_t)(wc * 32 + nt * 8 + r8) * 128u;

    float c[4][4][4];
    #pragma unroll
    for (int mt = 0; mt < 4; mt++)
        #pragma unroll
        for (int nt = 0; nt < 4; nt++)
            #pragma unroll
            for (int j = 0; j < 4; j++) c[mt][nt][j] = 0.f;

    int stage = 0;
    for (int i = 0; i < T; i++) {
        cp_wait<1>();
        __syncthreads();
        if (i + 2 < T) {
            int ws = stage + 2; if (ws >= 3) ws -= 3;
            uint32_t sA = sbase + (uint32_t)ws * 32768u, sB = sA + 16384u;
            #pragma unroll
            for (int s = 0; s < 4; s++) {
                cp16(sA + poff[s], Ap + (i + 2) * 64 + s * 8);
                cp16(sB + poff[s], Bp + (i + 2) * 64 + s * 8);
            }
        }
        cp_commit();

        const uint32_t AsB = sbase + (uint32_t)stage * 32768u;
        const uint32_t BsB = AsB + 16384u;
        #pragma unroll
        for (int kk = 0; kk < 4; kk++) {
            const uint32_t aOff = (((uint32_t)kk * 8u + aKC) ^ xw) * 4u;
            const uint32_t bOff = (((uint32_t)kk * 8u + bKC) ^ xw) * 4u;
            uint32_t af[4][4], bf[4][2];
            #pragma unroll
            for (int mt = 0; mt < 4; mt++)
                ldsm4(af[mt], AsB + aRow[mt] + aOff);
            #pragma unroll
            for (int nt = 0; nt < 4; nt++)
                ldsm2(bf[nt], BsB + bRow[nt] + bOff);
            #pragma unroll
            for (int mt = 0; mt < 4; mt++)
                #pragma unroll
                for (int nt = 0; nt < 4; nt++)
                    mma16(c[mt][nt], af[mt], bf[nt]);
        }
        stage = (stage == 2) ? 0 : stage + 1;
    }

    // ---------------- epilogue ----------------
    #pragma unroll
    for (int mt = 0; mt < 4; mt++) {
        #pragma unroll
        for (int rr = 0; rr < 2; rr++) {
            const int gm = rowBase + wr * 64 + mt * 16 + ra + rr * 8;
            int wb = 0, n = 0; size_t orow = 0;
            if (MODE == 0) { wb = gm / 49; n = gm - wb * 49; }
            if (MODE == 1) {
                wb = gm / 49; n = gm - wb * 49;
                int b = wb >> 6; int widx = wb & 63;
                int ii = (widx >> 3) * 7 + n / 7;
                int jj = (widx & 7) * 7 + n % 7;
                int oi = ii + 3; if (oi >= 56) oi -= 56;
                int oj = jj + 3; if (oj >= 56) oj -= 56;
                orow = ((size_t)b * 3136 + oi * 56 + oj) * 256;
            }
            if (MODE == 2 || MODE == 3) orow = (size_t)gm * ldo;

            #pragma unroll
            for (int nt = 0; nt < 4; nt++) {
                const int gc = colBase + wc * 32 + nt * 8 + 2 * ca;
                float2 bb = *(const float2*)(bias + gc);
                float v0 = c[mt][nt][rr * 2 + 0] + bb.x;
                float v1 = c[mt][nt][rr * 2 + 1] + bb.y;

                if (MODE == 0) {
                    int part = gc >> 8;
                    int hh = (gc >> 5) & 7;
                    int dd = gc & 31;
                    float* Op = (part == 0) ? O0 : ((part == 1) ? O1 : O2);
                    if (part == 0) { v0 *= SCALE; v1 *= SCALE; }
                    *(float2*)(Op + (((size_t)wb * 8 + hh) * 49 + n) * 32 + dd)
                        = make_float2(to_tf32(v0), to_tf32(v1));
                } else if (MODE == 1) {
                    float2 rr2 = *(const float2*)(res + orow + gc);
                    *(float2*)(O0 + orow + gc) = make_float2(rr2.x + v0, rr2.y + v1);
                } else if (MODE == 2) {
                    v0 = 0.5f * v0 * (1.0f + erff(v0 * 0.70710678118654752f));
                    v1 = 0.5f * v1 * (1.0f + erff(v1 * 0.70710678118654752f));
                    *(uint32_t*)(Ob + orow + gc) = bfp(v0, v1);
                } else {
                    float2 rr2 = *(const float2*)(res + orow + gc);
                    *(float2*)(O0 + orow + gc) = make_float2(rr2.x + v0, rr2.y + v1);
                }
            }
        }
    }
}

// ----------------------------------------------------------------------------
extern "C" void kernel_launch(void* const* d_in, const int* in_sizes, int n_in,
                              void* d_out, int out_size)
{
    const float* x      = (const float*)d_in[0];
    const float* mask   = (const float*)d_in[1];
    const float* n1g    = (const float*)d_in[2];
    const float* n1b    = (const float*)d_in[3];
    const float* qkv_w  = (const float*)d_in[4];
    const float* qkv_b  = (const float*)d_in[5];
    const float* relb   = (const float*)d_in[6];
    const float* proj_w = (const float*)d_in[7];
    const float* proj_b = (const float*)d_in[8];
    const float* n2g    = (const float*)d_in[9];
    const float* n2b    = (const float*)d_in[10];
    const float* fc1_w  = (const float*)d_in[11];
    const float* fc1_b  = (const float*)d_in[12];
    const float* fc2_w  = (const float*)d_in[13];
    const float* fc2_b  = (const float*)d_in[14];
    float* out = (float*)d_out;

    float *p_q, *p_k, *p_v, *p_x2, *p_btile;
    __nv_bfloat16 *p_hw, *p_o, *p_h2n, *p_mlp;
    __nv_bfloat16 *p_wqkv, *p_wprj, *p_wfc1, *p_wfc2;
    cudaGetSymbolAddress((void**)&p_q,     g_q);
    cudaGetSymbolAddress((void**)&p_k,     g_k);
    cudaGetSymbolAddress((void**)&p_v,     g_v);
    cudaGetSymbolAddress((void**)&p_x2,    g_x2);
    cudaGetSymbolAddress((void**)&p_btile, g_btile);
    cudaGetSymbolAddress((void**)&p_hw,    g_hw_bf);
    cudaGetSymbolAddress((void**)&p_o,     g_o_bf);
    cudaGetSymbolAddress((void**)&p_h2n,   g_h2n_bf);
    cudaGetSymbolAddress((void**)&p_mlp,   g_mlp_bf);
    cudaGetSymbolAddress((void**)&p_wqkv,  g_wqkv_bf);
    cudaGetSymbolAddress((void**)&p_wprj,  g_wprj_bf);
    cudaGetSymbolAddress((void**)&p_wfc1,  g_wfc1_bf);
    cudaGetSymbolAddress((void**)&p_wfc2,  g_wfc2_bf);

    cudaFuncSetAttribute(mma_gemm<0>, cudaFuncAttributeMaxDynamicSharedMemorySize, GEMM_SMEM);
    cudaFuncSetAttribute(mma_gemm<1>, cudaFuncAttributeMaxDynamicSharedMemorySize, GEMM_SMEM);
    cudaFuncSetAttribute(mma_gemm<2>, cudaFuncAttributeMaxDynamicSharedMemorySize, GEMM_SMEM);
    cudaFuncSetAttribute(mma_gemm<3>, cudaFuncAttributeMaxDynamicSharedMemorySize, GEMM_SMEM);

    wcvt_all<<<768, 256>>>((const float4*)qkv_w, (const float4*)proj_w,
                           (const float4*)fc1_w, (const float4*)fc2_w,
                           (uint2*)p_wqkv, (uint2*)p_wprj,
                           (uint2*)p_wfc1, (uint2*)p_wfc2);
    bias_prep<<<512, 256>>>(relb, mask, p_btile);
    // 1. LN1 + shift + window partition -> bf16
    ln_kernel<<<TOKENS / 8, 256>>>(x, p_hw, n1g, n1b, 1);
    // 2. QKV (bf16 mma) -> q(scaled)/k/v f32 in (wb,h,n,d)
    mma_gemm<0><<<dim3(6, 392), 256, GEMM_SMEM>>>(p_hw, p_wqkv, qkv_b, nullptr,
                                                  p_q, p_k, p_v, nullptr, 256, 0);
    // 3. Windowed MSA (tf32 tensor-core) -> bf16
    attn_mma<<<8192, 128>>>(p_btile);
    // 4. proj (bf16 mma) + window-reverse + un-roll + residual(x) -> f32
    mma_gemm<1><<<dim3(2, 392), 256, GEMM_SMEM>>>(p_o, p_wprj, proj_b, x,
                                                  p_x2, nullptr, nullptr, nullptr, 256, 256);
    // 5. LN2 -> bf16
    ln_kernel<<<TOKENS / 8, 256>>>(p_x2, p_h2n, n2g, n2b, 0);
    // 6. fc1 (bf16 mma) + GELU -> bf16
    mma_gemm<2><<<dim3(8, 392), 256, GEMM_SMEM>>>(p_h2n, p_wfc1, fc1_b, nullptr,
                                                  nullptr, nullptr, nullptr, p_mlp, 256, 1024);
    // 7. fc2 (bf16 mma) + residual(x2) -> out
    mma_gemm<3><<<dim3(2, 392), 256, GEMM_SMEM>>>(p_mlp, p_wfc2, fc2_b, p_x2,
                                                  out, nullptr, nullptr, nullptr, 1024, 256);
}